// round 5
// baseline (speedup 1.0000x reference)
#include <cuda_runtime.h>
#include <cstdint>

typedef unsigned long long ull;

// ---------------------------------------------------------------------------
// Scratch (device globals; no allocation anywhere)
// ---------------------------------------------------------------------------
__device__ float g_x256[2 * 256 * 256];
__device__ float g_x128[2 * 128 * 128];
__device__ float g_x64 [2 * 64 * 64];
__device__ float g_h1 [(size_t)2 * 64 * 512 * 512];
__device__ float g_h2 [(size_t)2 * 64 * 512 * 512];
__device__ float g_f  [(size_t)2 * 81 * 512 * 512];
__device__ float g_cat[(size_t)2 * 5  * 512 * 512];

// ---------------------------------------------------------------------------
// Packed f32x2 helpers (sm_103a FFMA2 path)
// ---------------------------------------------------------------------------
__device__ __forceinline__ void ffma2(ull& acc, ull a, ull b) {
    asm("fma.rn.f32x2 %0, %1, %2, %0;" : "+l"(acc) : "l"(a), "l"(b));
}
__device__ __forceinline__ ull packdup(float v) {
    ull r;
    asm("mov.b64 %0, {%1, %1};" : "=l"(r) : "f"(v));
    return r;
}
__device__ __forceinline__ void unpack2(ull v, float& lo, float& hi) {
    asm("mov.b64 {%0, %1}, %2;" : "=f"(lo), "=f"(hi) : "l"(v));
}

// ---------------------------------------------------------------------------
// Nearest-neighbor downsample
// ---------------------------------------------------------------------------
__global__ void downsample_kernel(const float* __restrict__ in, float* __restrict__ out,
                                  int OH, int OW, int stride)
{
    int idx = blockIdx.x * blockDim.x + threadIdx.x;
    int n = blockIdx.y;
    if (idx >= OH * OW) return;
    int oy = idx / OW, ox = idx - oy * OW;
    out[(size_t)n * OH * OW + idx] =
        in[(size_t)n * 512 * 512 + (size_t)(oy * stride) * 512 + ox * stride];
}

// ---------------------------------------------------------------------------
// Generic direct 3x3 SAME conv, packed-f32x2, 4 pixels/thread.
// 128 threads; output tile 32 wide x 16 high. Thread (px,ty): px=t&7 owns
// pixels 4px..4px+3 of row ty=t>>3. COUT in groups of GP channel-pairs
// (f32x2 lanes = co even/odd). 2 input channels per barrier stage,
// double-buffered smem, global->reg prefetch overlapping compute.
// ---------------------------------------------------------------------------
template<int COUT, bool RELU>
__global__ __launch_bounds__(128, 3)
void conv3x3_kernel(const float* __restrict__ in, const float* __restrict__ wt,
                    const float* __restrict__ bias, float* __restrict__ out,
                    int C, int H, int W)
{
    constexpr int GP = (COUT == 81) ? 7 : (COUT >= 64 ? 8 : (COUT + 1) / 2);
    constexpr int NPAIR = (COUT + 1) / 2;
    constexpr int NG = (NPAIR + GP - 1) / GP;
    constexpr int PS = 35;            // patch row stride (cols 0..33 valid)
    constexpr int ROWS = 18;          // 16 + halo 2
    constexpr int PELEM = ROWS * PS;  // 630
    constexpr int PITER = (PELEM + 127) / 128;
    constexpr int WELEM = GP * 18;
    constexpr int WITER = (WELEM + 127) / 128;

    __shared__ float patch[2][2][PELEM];
    __shared__ __align__(16) float ws[2][2][GP * 20];

    const int t  = threadIdx.x;
    const int px = t & 7;             // pixel quad: cols 4px..4px+3
    const int ty = t >> 3;            // 0..15
    const int x0 = blockIdx.x << 5;
    const int y0 = blockIdx.y << 4;
    const int n  = blockIdx.z;
    const size_t HW = (size_t)H * W;
    const int NS = (C + 1) / 2;

    const float* inn = in + (size_t)n * C * HW;

    float pv[2][PITER];
    float pw[2][WITER];

    auto prefetch = [&](int g, int s) {
#pragma unroll
        for (int ch = 0; ch < 2; ch++) {
            int c = 2 * s + ch;
            if (c < C) {
#pragma unroll
                for (int j = 0; j < PITER; j++) {
                    int e = t + j * 128;
                    float v = 0.f;
                    if (e < PELEM) {
                        int r = e / PS, cc = e - r * PS;
                        int gy = y0 + r - 1, gx = x0 + cc - 1;
                        if (cc < 34 && gy >= 0 && gy < H && gx >= 0 && gx < W)
                            v = inn[(size_t)c * HW + (size_t)gy * W + gx];
                    }
                    pv[ch][j] = v;
                }
#pragma unroll
                for (int j = 0; j < WITER; j++) {
                    pw[ch][j] = 0.f;
                    int e = t + j * 128;
                    if (e < WELEM) {
                        int p = e / 18, r = e - p * 18;
                        int lane = r / 9, k = r - lane * 9;
                        int co = 2 * (g * GP + p) + lane;
                        if (co < COUT)
                            pw[ch][j] = wt[((size_t)co * C + c) * 9 + k];
                    }
                }
            }
        }
    };

    auto store_sm = [&](int b, int s) {
#pragma unroll
        for (int ch = 0; ch < 2; ch++) {
            if (2 * s + ch < C) {
#pragma unroll
                for (int j = 0; j < PITER; j++) {
                    int e = t + j * 128;
                    if (e < PELEM) patch[b][ch][e] = pv[ch][j];
                }
#pragma unroll
                for (int j = 0; j < WITER; j++) {
                    int e = t + j * 128;
                    if (e < WELEM) {
                        int p = e / 18, r = e - p * 18;
                        int lane = r / 9, k = r - lane * 9;
                        ws[b][ch][p * 20 + 2 * k + lane] = pw[ch][j];
                    }
                }
            }
        }
    };

#pragma unroll 1
    for (int g = 0; g < NG; ++g) {
        ull acc[GP][4];
#pragma unroll
        for (int p = 0; p < GP; p++)
#pragma unroll
            for (int q = 0; q < 4; q++) acc[p][q] = 0ull;

        prefetch(g, 0);
#pragma unroll 1
        for (int s = 0; s < NS; ++s) {
            int b = s & 1;
            store_sm(b, s);
            __syncthreads();
            if (s + 1 < NS) prefetch(g, s + 1);

#pragma unroll
            for (int ch = 0; ch < 2; ch++) {
                if (2 * s + ch < C) {
                    const float* pb = patch[b][ch];
                    ull dup[3][6];
#pragma unroll
                    for (int ky = 0; ky < 3; ky++)
#pragma unroll
                        for (int j = 0; j < 6; j++)
                            dup[ky][j] = packdup(pb[(ty + ky) * PS + 4 * px + j]);

                    const float* wb = ws[b][ch];
#pragma unroll
                    for (int p = 0; p < GP; p++) {
                        ull w[9];
                        const ulonglong2* q2 = reinterpret_cast<const ulonglong2*>(wb + p * 20);
                        ulonglong2 q0 = q2[0], q1 = q2[1], qq2 = q2[2], q3 = q2[3];
                        w[0] = q0.x; w[1] = q0.y; w[2] = q1.x; w[3] = q1.y;
                        w[4] = qq2.x; w[5] = qq2.y; w[6] = q3.x; w[7] = q3.y;
                        w[8] = *reinterpret_cast<const ull*>(wb + p * 20 + 16);
#pragma unroll
                        for (int ky = 0; ky < 3; ky++)
#pragma unroll
                            for (int kx = 0; kx < 3; kx++)
#pragma unroll
                                for (int q = 0; q < 4; q++)
                                    ffma2(acc[p][q], dup[ky][kx + q], w[ky * 3 + kx]);
                    }
                }
            }
        }

        {
            const int oy = y0 + ty;
            const int ox = x0 + 4 * px;
            float* outp = out + (size_t)n * COUT * HW + (size_t)oy * W + ox;
#pragma unroll
            for (int p = 0; p < GP; p++) {
                int co0 = 2 * (g * GP + p);
                if (co0 < COUT) {
                    float lo[4], hi[4];
#pragma unroll
                    for (int q = 0; q < 4; q++) unpack2(acc[p][q], lo[q], hi[q]);
                    float bi0 = __ldg(&bias[co0]);
                    float4 r0;
                    r0.x = lo[0] + bi0; r0.y = lo[1] + bi0;
                    r0.z = lo[2] + bi0; r0.w = lo[3] + bi0;
                    if (RELU) {
                        r0.x = fmaxf(r0.x, 0.f); r0.y = fmaxf(r0.y, 0.f);
                        r0.z = fmaxf(r0.z, 0.f); r0.w = fmaxf(r0.w, 0.f);
                    }
                    *reinterpret_cast<float4*>(outp + (size_t)co0 * HW) = r0;
                    if (co0 + 1 < COUT) {
                        float bi1 = __ldg(&bias[co0 + 1]);
                        float4 r1;
                        r1.x = hi[0] + bi1; r1.y = hi[1] + bi1;
                        r1.z = hi[2] + bi1; r1.w = hi[3] + bi1;
                        if (RELU) {
                            r1.x = fmaxf(r1.x, 0.f); r1.y = fmaxf(r1.y, 0.f);
                            r1.z = fmaxf(r1.z, 0.f); r1.w = fmaxf(r1.w, 0.f);
                        }
                        *reinterpret_cast<float4*>(outp + (size_t)(co0 + 1) * HW) = r1;
                    }
                }
            }
        }
        __syncthreads();
    }
}

// ---------------------------------------------------------------------------
// Fused conv1(1->64,relu) + conv2(64->64,relu), 4 pixels/thread.
// Input patch loaded once; conv1 tiles recomputed in smem per stage/group;
// conv2 weights streamed global->reg->smem. No activation LDG in mainloop.
// ---------------------------------------------------------------------------
__global__ __launch_bounds__(128, 3)
void conv12_kernel(const float* __restrict__ x, const float* __restrict__ w1,
                   const float* __restrict__ b1, const float* __restrict__ w2,
                   const float* __restrict__ b2, float* __restrict__ out,
                   int H, int W)
{
    constexpr int GP = 8, NG = 4, COUT = 64;
    constexpr int PS = 35, ROWS = 18;            // conv1-out tile: 18 x 34
    constexpr int CELEM = ROWS * 34;             // 612 valid positions / channel
    constexpr int XPS = 37, XROWS = 20;          // input halo tile 20 x 36
    constexpr int XELEM = XROWS * XPS;           // 740
    constexpr int WELEM = GP * 18;               // 144

    __shared__ float xpatch[XELEM];
    __shared__ float w1s[64 * 10];
    __shared__ float cbuf[2][2][ROWS * PS];
    __shared__ __align__(16) float ws[2][2][GP * 20];

    const int t  = threadIdx.x;
    const int px = t & 7;
    const int ty = t >> 3;
    const int x0 = blockIdx.x << 5;
    const int y0 = blockIdx.y << 4;
    const int n  = blockIdx.z;
    const size_t HW = (size_t)H * W;

    // one-time loads
    const float* xn = x + (size_t)n * HW;
#pragma unroll
    for (int j = 0; j < 6; j++) {
        int e = t + j * 128;
        if (e < XELEM) {
            int r = e / XPS, cc = e - r * XPS;
            int gy = y0 + r - 2, gx = x0 + cc - 2;
            float v = 0.f;
            if (cc < 36 && gy >= 0 && gy < H && gx >= 0 && gx < W)
                v = xn[(size_t)gy * W + gx];
            xpatch[e] = v;
        }
    }
#pragma unroll
    for (int j = 0; j < 5; j++) {
        int e = t + j * 128;
        if (e < 640) {
            int c = e / 10, k = e - c * 10;
            w1s[e] = (k < 9) ? w1[c * 9 + k] : b1[c];
        }
    }
    __syncthreads();

    float pw[2][2];
    auto prefetch_w = [&](int g, int s) {
#pragma unroll
        for (int ch = 0; ch < 2; ch++) {
            int c = 2 * s + ch;
#pragma unroll
            for (int j = 0; j < 2; j++) {
                pw[ch][j] = 0.f;
                int e = t + j * 128;
                if (e < WELEM) {
                    int p = e / 18, r = e - p * 18;
                    int lane = r / 9, k = r - lane * 9;
                    int co = 2 * (g * GP + p) + lane;
                    pw[ch][j] = w2[((size_t)co * 64 + c) * 9 + k];
                }
            }
        }
    };

#pragma unroll 1
    for (int g = 0; g < NG; ++g) {
        ull acc[GP][4];
#pragma unroll
        for (int p = 0; p < GP; p++)
#pragma unroll
            for (int q = 0; q < 4; q++) acc[p][q] = 0ull;

        prefetch_w(g, 0);
#pragma unroll 1
        for (int s = 0; s < 32; ++s) {
            int b = s & 1;
            // produce conv1 channels 2s, 2s+1 over 18 x 34 halo region
#pragma unroll
            for (int j = 0; j < 10; j++) {
                int e = t + j * 128;
                if (e < 2 * CELEM) {
                    int ch = e / CELEM, rr = e - ch * CELEM;
                    int r = rr / 34, col = rr - r * 34;
                    int c = 2 * s + ch;
                    int gy = y0 + r - 1, gx = x0 + col - 1;
                    float v = 0.f;
                    if (gy >= 0 && gy < H && gx >= 0 && gx < W) {
                        const float* wp = &w1s[c * 10];
                        float a = wp[9];
#pragma unroll
                        for (int dy = 0; dy < 3; dy++)
#pragma unroll
                            for (int dx = 0; dx < 3; dx++)
                                a += xpatch[(r + dy) * XPS + col + dx] * wp[dy * 3 + dx];
                        v = fmaxf(a, 0.f);
                    }
                    cbuf[b][ch][r * PS + col] = v;
                }
            }
            // stage conv2 weights
#pragma unroll
            for (int ch = 0; ch < 2; ch++)
#pragma unroll
                for (int j = 0; j < 2; j++) {
                    int e = t + j * 128;
                    if (e < WELEM) {
                        int p = e / 18, r = e - p * 18;
                        int lane = r / 9, k = r - lane * 9;
                        ws[b][ch][p * 20 + 2 * k + lane] = pw[ch][j];
                    }
                }
            __syncthreads();
            if (s + 1 < 32) prefetch_w(g, s + 1);

#pragma unroll
            for (int ch = 0; ch < 2; ch++) {
                const float* pb = cbuf[b][ch];
                ull dup[3][6];
#pragma unroll
                for (int ky = 0; ky < 3; ky++)
#pragma unroll
                    for (int j = 0; j < 6; j++)
                        dup[ky][j] = packdup(pb[(ty + ky) * PS + 4 * px + j]);

                const float* wb = ws[b][ch];
#pragma unroll
                for (int p = 0; p < GP; p++) {
                    ull w[9];
                    const ulonglong2* q2 = reinterpret_cast<const ulonglong2*>(wb + p * 20);
                    ulonglong2 q0 = q2[0], q1 = q2[1], qq2 = q2[2], q3 = q2[3];
                    w[0] = q0.x; w[1] = q0.y; w[2] = q1.x; w[3] = q1.y;
                    w[4] = qq2.x; w[5] = qq2.y; w[6] = q3.x; w[7] = q3.y;
                    w[8] = *reinterpret_cast<const ull*>(wb + p * 20 + 16);
#pragma unroll
                    for (int ky = 0; ky < 3; ky++)
#pragma unroll
                        for (int kx = 0; kx < 3; kx++)
#pragma unroll
                            for (int q = 0; q < 4; q++)
                                ffma2(acc[p][q], dup[ky][kx + q], w[ky * 3 + kx]);
                }
            }
        }

        {
            const int oy = y0 + ty;
            const int ox = x0 + 4 * px;
            float* outp = out + (size_t)n * COUT * HW + (size_t)oy * W + ox;
#pragma unroll
            for (int p = 0; p < GP; p++) {
                int co0 = 2 * (g * GP + p);
                float lo[4], hi[4];
#pragma unroll
                for (int q = 0; q < 4; q++) unpack2(acc[p][q], lo[q], hi[q]);
                float bi0 = __ldg(&b2[co0]);
                float bi1 = __ldg(&b2[co0 + 1]);
                float4 r0, r1;
                r0.x = fmaxf(lo[0] + bi0, 0.f); r0.y = fmaxf(lo[1] + bi0, 0.f);
                r0.z = fmaxf(lo[2] + bi0, 0.f); r0.w = fmaxf(lo[3] + bi0, 0.f);
                r1.x = fmaxf(hi[0] + bi1, 0.f); r1.y = fmaxf(hi[1] + bi1, 0.f);
                r1.z = fmaxf(hi[2] + bi1, 0.f); r1.w = fmaxf(hi[3] + bi1, 0.f);
                *reinterpret_cast<float4*>(outp + (size_t)co0 * HW) = r0;
                *reinterpret_cast<float4*>(outp + (size_t)(co0 + 1) * HW) = r1;
            }
        }
        __syncthreads();
    }
}

// ---------------------------------------------------------------------------
// Softmax(81) + 9x9 dynamic conv + nearest upsample into concat channel
// ---------------------------------------------------------------------------
__global__ __launch_bounds__(128)
void softmax_apply_kernel(const float* __restrict__ f, const float* __restrict__ s,
                          float* __restrict__ cat, int H, int W, int ch, int factor)
{
    int idx = blockIdx.x * blockDim.x + threadIdx.x;
    int n = blockIdx.y;
    if (idx >= H * W) return;
    int iy = idx / W, ix = idx - iy * W;

    const float* fn = f + (size_t)n * 81 * H * W + idx;
    float lg[81];
    float mx = -1e30f;
#pragma unroll
    for (int k = 0; k < 81; k++) {
        lg[k] = fn[(size_t)k * H * W];
        mx = fmaxf(mx, lg[k]);
    }
    float sum = 0.f;
#pragma unroll
    for (int k = 0; k < 81; k++) {
        lg[k] = __expf(lg[k] - mx);
        sum += lg[k];
    }
    float inv = 1.f / sum;

    const float* sn = s + (size_t)n * H * W;
    float outv = 0.f;
#pragma unroll
    for (int dy = 0; dy < 9; dy++) {
        int yy = iy + dy - 4;
#pragma unroll
        for (int dx = 0; dx < 9; dx++) {
            int xx = ix + dx - 4;
            float xv = (yy >= 0 && yy < H && xx >= 0 && xx < W)
                         ? sn[(size_t)yy * W + xx] : 0.f;
            outv += lg[dy * 9 + dx] * xv;
        }
    }
    outv *= inv;

    float* cn = cat + ((size_t)n * 5 + ch) * 512 * 512;
    int oy0 = iy * factor, ox0 = ix * factor;
    for (int ry = 0; ry < factor; ry++)
        for (int rx = 0; rx < factor; rx++)
            cn[(size_t)(oy0 + ry) * 512 + ox0 + rx] = outv;
}

// ---------------------------------------------------------------------------
// Launch
// ---------------------------------------------------------------------------
extern "C" void kernel_launch(void* const* d_in, const int* in_sizes, int n_in,
                              void* d_out, int out_size)
{
    const float* x   = (const float*)d_in[0];
    const float* g   = (const float*)d_in[1];
    const float* fWa = (const float*)d_in[2];
    const float* fba = (const float*)d_in[3];
    const float* fWb = (const float*)d_in[4];
    const float* fbb = (const float*)d_in[5];
    const float* fWc = (const float*)d_in[6];
    const float* fbc = (const float*)d_in[7];
    const float* W2a = (const float*)d_in[8];
    const float* b2a = (const float*)d_in[9];
    const float* W2b = (const float*)d_in[10];
    const float* b2b = (const float*)d_in[11];
    float* out = (float*)d_out;

    float *x256, *x128, *x64p, *h1, *h2, *fbuf, *cat;
    cudaGetSymbolAddress((void**)&x256, g_x256);
    cudaGetSymbolAddress((void**)&x128, g_x128);
    cudaGetSymbolAddress((void**)&x64p, g_x64);
    cudaGetSymbolAddress((void**)&h1,   g_h1);
    cudaGetSymbolAddress((void**)&h2,   g_h2);
    cudaGetSymbolAddress((void**)&fbuf, g_f);
    cudaGetSymbolAddress((void**)&cat,  g_cat);

    downsample_kernel<<<dim3((256 * 256 + 255) / 256, 2), 256>>>(x, x256, 256, 256, 2);
    downsample_kernel<<<dim3((128 * 128 + 255) / 256, 2), 256>>>(x, x128, 128, 128, 4);
    downsample_kernel<<<dim3((64 * 64 + 255) / 256, 2), 256>>>(x, x64p, 64, 64, 8);

    const float* sin[5] = { x, x256, x128, x64p, g };
    const int    hs[5]  = { 512, 256, 128, 64, 512 };

    for (int i = 0; i < 5; i++) {
        int H = hs[i], W = H;
        dim3 grid(W / 32, H / 16, 2);
        conv12_kernel<<<grid, 128>>>(
            sin[i], fWa + (size_t)i * 64 * 9, fba + i * 64,
            fWb + (size_t)i * 64 * 64 * 9, fbb + i * 64, h2, H, W);
        conv3x3_kernel<81, false><<<grid, 128>>>(
            h2, fWc + (size_t)i * 81 * 64 * 9, fbc + i * 81, fbuf, 64, H, W);
        int np = H * W;
        softmax_apply_kernel<<<dim3((np + 127) / 128, 2), 128>>>(
            fbuf, sin[i], cat, H, W, i, 512 / H);
    }

    dim3 gridF(512 / 32, 512 / 16, 2);
    conv3x3_kernel<64, true><<<gridF, 128>>>(cat, W2a, b2a, h1, 5, 512, 512);
    conv3x3_kernel<1, false><<<gridF, 128>>>(h1, W2b, b2b, out, 64, 512, 512);
}

// round 7
// speedup vs baseline: 1.1331x; 1.1331x over previous
#include <cuda_runtime.h>
#include <cstdint>

typedef unsigned long long ull;

// ---------------------------------------------------------------------------
// Scratch (device globals; no allocation anywhere)
// ---------------------------------------------------------------------------
__device__ float g_x256[2 * 256 * 256];
__device__ float g_x128[2 * 128 * 128];
__device__ float g_x64 [2 * 64 * 64];
__device__ float g_h1 [(size_t)2 * 64 * 512 * 512];
__device__ float g_h2 [(size_t)2 * 64 * 512 * 512];
__device__ float g_f  [(size_t)2 * 81 * 512 * 512];
__device__ float g_cat[(size_t)2 * 5  * 512 * 512];

// ---------------------------------------------------------------------------
// Packed f32x2 helpers (sm_103a FFMA2 path)
// ---------------------------------------------------------------------------
__device__ __forceinline__ void ffma2(ull& acc, ull a, ull b) {
    asm("fma.rn.f32x2 %0, %1, %2, %0;" : "+l"(acc) : "l"(a), "l"(b));
}
__device__ __forceinline__ ull packdup(float v) {
    ull r;
    asm("mov.b64 %0, {%1, %1};" : "=l"(r) : "f"(v));
    return r;
}
__device__ __forceinline__ ull pack2(float lo, float hi) {
    ull r;
    asm("mov.b64 %0, {%1, %2};" : "=l"(r) : "f"(lo), "f"(hi));
    return r;
}
__device__ __forceinline__ void unpack2(ull v, float& lo, float& hi) {
    asm("mov.b64 {%0, %1}, %2;" : "=f"(lo), "=f"(hi) : "l"(v));
}

// ---------------------------------------------------------------------------
// Nearest-neighbor downsample
// ---------------------------------------------------------------------------
__global__ void downsample_kernel(const float* __restrict__ in, float* __restrict__ out,
                                  int OH, int OW, int stride)
{
    int idx = blockIdx.x * blockDim.x + threadIdx.x;
    int n = blockIdx.y;
    if (idx >= OH * OW) return;
    int oy = idx / OW, ox = idx - oy * OW;
    out[(size_t)n * OH * OW + idx] =
        in[(size_t)n * 512 * 512 + (size_t)(oy * stride) * 512 + ox * stride];
}

// ---------------------------------------------------------------------------
// Generic direct 3x3 SAME conv, packed-f32x2 math, 2 pixels/thread.
// 128 threads; output tile 32x8. Patch smem is CHANNEL-PAIR INTERLEAVED
// (float2 per position: lanes = channels 2s, 2s+1), so one LDS.64 feeds both
// channels of a stage. COUT in groups of GP channel-pairs (f32x2 lanes = co
// even/odd). 2 input channels per barrier stage, double-buffered smem,
// global->reg prefetch overlapping compute.
// ---------------------------------------------------------------------------
template<int COUT, bool RELU>
__global__ __launch_bounds__(128, 3)
void conv3x3_kernel(const float* __restrict__ in, const float* __restrict__ wt,
                    const float* __restrict__ bias, float* __restrict__ out,
                    int C, int H, int W)
{
    constexpr int GP = (COUT == 81) ? 14 : (COUT >= 64 ? 16 : (COUT + 1) / 2);
    constexpr int NPAIR = (COUT + 1) / 2;
    constexpr int NG = (NPAIR + GP - 1) / GP;
    constexpr int PS = 35;            // patch row stride (cols 0..33 valid)
    constexpr int ROWS = 10;          // 8 + halo 2
    constexpr int PELEM = ROWS * PS;  // 350
    constexpr int WELEM = GP * 18;
    constexpr int WITER = (WELEM + 127) / 128;

    __shared__ float2 patch2[2][PELEM];
    __shared__ __align__(16) float ws[2][2][GP * 20];

    const int t  = threadIdx.x;
    const int px = t & 15;            // pixel pair: cols 2px, 2px+1
    const int ty = t >> 4;            // 0..7
    const int x0 = blockIdx.x << 5;
    const int y0 = blockIdx.y << 3;
    const int n  = blockIdx.z;
    const size_t HW = (size_t)H * W;
    const int NS = (C + 1) / 2;

    const float* inn = in + (size_t)n * C * HW;

    float pv[2][3];
    float pw[2][WITER];

    auto prefetch = [&](int g, int s) {
#pragma unroll
        for (int ch = 0; ch < 2; ch++) {
            int c = 2 * s + ch;
#pragma unroll
            for (int j = 0; j < 3; j++) {
                float v = 0.f;
                int e = t + j * 128;
                if (c < C && e < PELEM) {
                    int r = e / PS, cc = e - r * PS;
                    int gy = y0 + r - 1, gx = x0 + cc - 1;
                    if (cc < 34 && gy >= 0 && gy < H && gx >= 0 && gx < W)
                        v = inn[(size_t)c * HW + (size_t)gy * W + gx];
                }
                pv[ch][j] = v;
            }
#pragma unroll
            for (int j = 0; j < WITER; j++) {
                pw[ch][j] = 0.f;
                int e = t + j * 128;
                if (c < C && e < WELEM) {
                    int p = e / 18, r = e - p * 18;
                    int lane = r / 9, k = r - lane * 9;
                    int co = 2 * (g * GP + p) + lane;
                    if (co < COUT)
                        pw[ch][j] = wt[((size_t)co * C + c) * 9 + k];
                }
            }
        }
    };

    auto store_sm = [&](int b, int s) {
#pragma unroll
        for (int j = 0; j < 3; j++) {
            int e = t + j * 128;
            if (e < PELEM) patch2[b][e] = make_float2(pv[0][j], pv[1][j]);
        }
#pragma unroll
        for (int ch = 0; ch < 2; ch++)
#pragma unroll
            for (int j = 0; j < WITER; j++) {
                int e = t + j * 128;
                if (e < WELEM) {
                    int p = e / 18, r = e - p * 18;
                    int lane = r / 9, k = r - lane * 9;
                    ws[b][ch][p * 20 + 2 * k + lane] = pw[ch][j];
                }
            }
    };

#pragma unroll 1
    for (int g = 0; g < NG; ++g) {
        ull accA[GP], accB[GP];
#pragma unroll
        for (int p = 0; p < GP; p++) { accA[p] = 0ull; accB[p] = 0ull; }

        prefetch(g, 0);
#pragma unroll 1
        for (int s = 0; s < NS; ++s) {
            int b = s & 1;
            store_sm(b, s);
            __syncthreads();
            if (s + 1 < NS) prefetch(g, s + 1);

            // one LDS.64 per position feeds both channels of this stage
            const float2* pb = patch2[b];
            float2 v2[12];
#pragma unroll
            for (int ky = 0; ky < 3; ky++)
#pragma unroll
                for (int j = 0; j < 4; j++)
                    v2[ky * 4 + j] = pb[(ty + ky) * PS + 2 * px + j];

#pragma unroll
            for (int ch = 0; ch < 2; ch++) {
                if (2 * s + ch < C) {
                    ull dup[12];
#pragma unroll
                    for (int i = 0; i < 12; i++)
                        dup[i] = packdup(ch ? v2[i].y : v2[i].x);

                    const float* wb = ws[b][ch];
#pragma unroll
                    for (int p = 0; p < GP; p++) {
                        ull w[9];
                        const ulonglong2* q = reinterpret_cast<const ulonglong2*>(wb + p * 20);
                        ulonglong2 q0 = q[0], q1 = q[1], q2 = q[2], q3 = q[3];
                        w[0] = q0.x; w[1] = q0.y; w[2] = q1.x; w[3] = q1.y;
                        w[4] = q2.x; w[5] = q2.y; w[6] = q3.x; w[7] = q3.y;
                        w[8] = *reinterpret_cast<const ull*>(wb + p * 20 + 16);
#pragma unroll
                        for (int ky = 0; ky < 3; ky++)
#pragma unroll
                            for (int kx = 0; kx < 3; kx++) {
                                ffma2(accA[p], dup[ky * 4 + kx],     w[ky * 3 + kx]);
                                ffma2(accB[p], dup[ky * 4 + kx + 1], w[ky * 3 + kx]);
                            }
                    }
                }
            }
        }

        {
            const int oy = y0 + ty;
            const int ox = x0 + 2 * px;
            float* outp = out + (size_t)n * COUT * HW + (size_t)oy * W + ox;
#pragma unroll
            for (int p = 0; p < GP; p++) {
                int co0 = 2 * (g * GP + p);
                if (co0 < COUT) {
                    float a0, a1, b0, b1;
                    unpack2(accA[p], a0, a1);
                    unpack2(accB[p], b0, b1);
                    float bi0 = __ldg(&bias[co0]);
                    float r0 = a0 + bi0, r1 = b0 + bi0;
                    if (RELU) { r0 = fmaxf(r0, 0.f); r1 = fmaxf(r1, 0.f); }
                    *reinterpret_cast<float2*>(outp + (size_t)co0 * HW) = make_float2(r0, r1);
                    if (co0 + 1 < COUT) {
                        float bi1 = __ldg(&bias[co0 + 1]);
                        float s0 = a1 + bi1, s1 = b1 + bi1;
                        if (RELU) { s0 = fmaxf(s0, 0.f); s1 = fmaxf(s1, 0.f); }
                        *reinterpret_cast<float2*>(outp + (size_t)(co0 + 1) * HW) = make_float2(s0, s1);
                    }
                }
            }
        }
        __syncthreads();
    }
}

// ---------------------------------------------------------------------------
// Fused conv1(1->64,relu) + conv2(64->64,relu), 2 pixels/thread.
// Input patch loaded once. Conv1 recompute is PACKED f32x2 over the stage's
// channel pair: xpatch reads shared by both channels, conv1 weights one
// broadcast LDS.64 per tap hoisted per stage. cbuf is channel-pair
// interleaved float2 so consume needs one LDS.64 per position.
// ---------------------------------------------------------------------------
__global__ __launch_bounds__(128, 3)
void conv12_kernel(const float* __restrict__ x, const float* __restrict__ w1,
                   const float* __restrict__ b1, const float* __restrict__ w2,
                   const float* __restrict__ b2, float* __restrict__ out,
                   int H, int W)
{
    constexpr int GP = 16, NG = 2, COUT = 64;
    constexpr int PS = 35, ROWS = 10;           // conv1-out tile 10 x 34
    constexpr int CELEM = ROWS * 34;            // 340 pair-positions
    constexpr int XPS = 37, XROWS = 12;
    constexpr int XELEM = XROWS * XPS;          // 444
    constexpr int WELEM = GP * 18;              // 288

    __shared__ float xpatch[XELEM];
    __shared__ ull w1pk[32 * 10];               // f32x2 taps+bias per channel pair
    __shared__ float2 cbuf2[2][ROWS * PS];
    __shared__ __align__(16) float ws[2][2][GP * 20];

    const int t  = threadIdx.x;
    const int px = t & 15;
    const int ty = t >> 4;
    const int x0 = blockIdx.x << 5;
    const int y0 = blockIdx.y << 3;
    const int n  = blockIdx.z;
    const size_t HW = (size_t)H * W;

    // one-time loads
    const float* xn = x + (size_t)n * HW;
#pragma unroll
    for (int j = 0; j < 4; j++) {
        int e = t + j * 128;
        if (e < XELEM) {
            int r = e / XPS, cc = e - r * XPS;
            int gy = y0 + r - 2, gx = x0 + cc - 2;
            float v = 0.f;
            if (cc < 36 && gy >= 0 && gy < H && gx >= 0 && gx < W)
                v = xn[(size_t)gy * W + gx];
            xpatch[e] = v;
        }
    }
#pragma unroll
    for (int j = 0; j < 3; j++) {
        int e = t + j * 128;
        if (e < 320) {
            int cp = e / 10, k = e - cp * 10;
            float lo, hi;
            if (k < 9) { lo = w1[(2 * cp) * 9 + k]; hi = w1[(2 * cp + 1) * 9 + k]; }
            else       { lo = b1[2 * cp];           hi = b1[2 * cp + 1]; }
            w1pk[e] = pack2(lo, hi);
        }
    }
    __syncthreads();

    float pw[2][3];
    auto prefetch_w = [&](int g, int s) {
#pragma unroll
        for (int ch = 0; ch < 2; ch++) {
            int c = 2 * s + ch;
#pragma unroll
            for (int j = 0; j < 3; j++) {
                pw[ch][j] = 0.f;
                int e = t + j * 128;
                if (e < WELEM) {
                    int p = e / 18, r = e - p * 18;
                    int lane = r / 9, k = r - lane * 9;
                    int co = 2 * (g * GP + p) + lane;
                    pw[ch][j] = w2[((size_t)co * 64 + c) * 9 + k];
                }
            }
        }
    };

#pragma unroll 1
    for (int g = 0; g < NG; ++g) {
        ull accA[GP], accB[GP];
#pragma unroll
        for (int p = 0; p < GP; p++) { accA[p] = 0ull; accB[p] = 0ull; }

        prefetch_w(g, 0);
#pragma unroll 1
        for (int s = 0; s < 32; ++s) {
            int b = s & 1;

            // stage weights for conv1 channel pair s (broadcast, hoisted)
            ull w1r[10];
#pragma unroll
            for (int k = 0; k < 10; k++) w1r[k] = w1pk[s * 10 + k];

            // produce conv1 channels 2s,2s+1 packed over the 10x34 halo region
#pragma unroll
            for (int j = 0; j < 3; j++) {
                int e = t + j * 128;
                if (e < CELEM) {
                    int r = e / 34, col = e - r * 34;
                    int gy = y0 + r - 1, gx = x0 + col - 1;
                    float2 v = make_float2(0.f, 0.f);
                    if (gy >= 0 && gy < H && gx >= 0 && gx < W) {
                        ull a = w1r[9];
#pragma unroll
                        for (int dy = 0; dy < 3; dy++)
#pragma unroll
                            for (int dx = 0; dx < 3; dx++)
                                ffma2(a, packdup(xpatch[(r + dy) * XPS + col + dx]),
                                      w1r[dy * 3 + dx]);
                        float lo, hi;
                        unpack2(a, lo, hi);
                        v = make_float2(fmaxf(lo, 0.f), fmaxf(hi, 0.f));
                    }
                    cbuf2[b][r * PS + col] = v;
                }
            }
            // stage conv2 weights
#pragma unroll
            for (int ch = 0; ch < 2; ch++)
#pragma unroll
                for (int j = 0; j < 3; j++) {
                    int e = t + j * 128;
                    if (e < WELEM) {
                        int p = e / 18, r = e - p * 18;
                        int lane = r / 9, k = r - lane * 9;
                        ws[b][ch][p * 20 + 2 * k + lane] = pw[ch][j];
                    }
                }
            __syncthreads();
            if (s + 1 < 32) prefetch_w(g, s + 1);

            const float2* pb = cbuf2[b];
            float2 v2[12];
#pragma unroll
            for (int ky = 0; ky < 3; ky++)
#pragma unroll
                for (int j = 0; j < 4; j++)
                    v2[ky * 4 + j] = pb[(ty + ky) * PS + 2 * px + j];

#pragma unroll
            for (int ch = 0; ch < 2; ch++) {
                ull dup[12];
#pragma unroll
                for (int i = 0; i < 12; i++)
                    dup[i] = packdup(ch ? v2[i].y : v2[i].x);

                const float* wb = ws[b][ch];
#pragma unroll
                for (int p = 0; p < GP; p++) {
                    ull w[9];
                    const ulonglong2* q = reinterpret_cast<const ulonglong2*>(wb + p * 20);
                    ulonglong2 q0 = q[0], q1 = q[1], q2 = q[2], q3 = q[3];
                    w[0] = q0.x; w[1] = q0.y; w[2] = q1.x; w[3] = q1.y;
                    w[4] = q2.x; w[5] = q2.y; w[6] = q3.x; w[7] = q3.y;
                    w[8] = *reinterpret_cast<const ull*>(wb + p * 20 + 16);
#pragma unroll
                    for (int ky = 0; ky < 3; ky++)
#pragma unroll
                        for (int kx = 0; kx < 3; kx++) {
                            ffma2(accA[p], dup[ky * 4 + kx],     w[ky * 3 + kx]);
                            ffma2(accB[p], dup[ky * 4 + kx + 1], w[ky * 3 + kx]);
                        }
                }
            }
        }

        {
            const int oy = y0 + ty;
            const int ox = x0 + 2 * px;
            float* outp = out + (size_t)n * COUT * HW + (size_t)oy * W + ox;
#pragma unroll
            for (int p = 0; p < GP; p++) {
                int co0 = 2 * (g * GP + p);
                float a0, a1, b0v, b1v;
                unpack2(accA[p], a0, a1);
                unpack2(accB[p], b0v, b1v);
                float bi0 = __ldg(&b2[co0]);
                float bi1 = __ldg(&b2[co0 + 1]);
                float r0 = fmaxf(a0 + bi0, 0.f), r1 = fmaxf(b0v + bi0, 0.f);
                float s0 = fmaxf(a1 + bi1, 0.f), s1 = fmaxf(b1v + bi1, 0.f);
                *reinterpret_cast<float2*>(outp + (size_t)co0 * HW) = make_float2(r0, r1);
                *reinterpret_cast<float2*>(outp + (size_t)(co0 + 1) * HW) = make_float2(s0, s1);
            }
        }
        __syncthreads();
    }
}

// ---------------------------------------------------------------------------
// Softmax(81) + 9x9 dynamic conv + nearest upsample into concat channel
// ---------------------------------------------------------------------------
__global__ __launch_bounds__(128)
void softmax_apply_kernel(const float* __restrict__ f, const float* __restrict__ s,
                          float* __restrict__ cat, int H, int W, int ch, int factor)
{
    int idx = blockIdx.x * blockDim.x + threadIdx.x;
    int n = blockIdx.y;
    if (idx >= H * W) return;
    int iy = idx / W, ix = idx - iy * W;

    const float* fn = f + (size_t)n * 81 * H * W + idx;
    float lg[81];
    float mx = -1e30f;
#pragma unroll
    for (int k = 0; k < 81; k++) {
        lg[k] = fn[(size_t)k * H * W];
        mx = fmaxf(mx, lg[k]);
    }
    float sum = 0.f;
#pragma unroll
    for (int k = 0; k < 81; k++) {
        lg[k] = __expf(lg[k] - mx);
        sum += lg[k];
    }
    float inv = 1.f / sum;

    const float* sn = s + (size_t)n * H * W;
    float outv = 0.f;
#pragma unroll
    for (int dy = 0; dy < 9; dy++) {
        int yy = iy + dy - 4;
#pragma unroll
        for (int dx = 0; dx < 9; dx++) {
            int xx = ix + dx - 4;
            float xv = (yy >= 0 && yy < H && xx >= 0 && xx < W)
                         ? sn[(size_t)yy * W + xx] : 0.f;
            outv += lg[dy * 9 + dx] * xv;
        }
    }
    outv *= inv;

    float* cn = cat + ((size_t)n * 5 + ch) * 512 * 512;
    int oy0 = iy * factor, ox0 = ix * factor;
    for (int ry = 0; ry < factor; ry++)
        for (int rx = 0; rx < factor; rx++)
            cn[(size_t)(oy0 + ry) * 512 + ox0 + rx] = outv;
}

// ---------------------------------------------------------------------------
// Launch
// ---------------------------------------------------------------------------
extern "C" void kernel_launch(void* const* d_in, const int* in_sizes, int n_in,
                              void* d_out, int out_size)
{
    const float* x   = (const float*)d_in[0];
    const float* g   = (const float*)d_in[1];
    const float* fWa = (const float*)d_in[2];
    const float* fba = (const float*)d_in[3];
    const float* fWb = (const float*)d_in[4];
    const float* fbb = (const float*)d_in[5];
    const float* fWc = (const float*)d_in[6];
    const float* fbc = (const float*)d_in[7];
    const float* W2a = (const float*)d_in[8];
    const float* b2a = (const float*)d_in[9];
    const float* W2b = (const float*)d_in[10];
    const float* b2b = (const float*)d_in[11];
    float* out = (float*)d_out;

    float *x256, *x128, *x64p, *h1, *h2, *fbuf, *cat;
    cudaGetSymbolAddress((void**)&x256, g_x256);
    cudaGetSymbolAddress((void**)&x128, g_x128);
    cudaGetSymbolAddress((void**)&x64p, g_x64);
    cudaGetSymbolAddress((void**)&h1,   g_h1);
    cudaGetSymbolAddress((void**)&h2,   g_h2);
    cudaGetSymbolAddress((void**)&fbuf, g_f);
    cudaGetSymbolAddress((void**)&cat,  g_cat);

    downsample_kernel<<<dim3((256 * 256 + 255) / 256, 2), 256>>>(x, x256, 256, 256, 2);
    downsample_kernel<<<dim3((128 * 128 + 255) / 256, 2), 256>>>(x, x128, 128, 128, 4);
    downsample_kernel<<<dim3((64 * 64 + 255) / 256, 2), 256>>>(x, x64p, 64, 64, 8);

    const float* sin[5] = { x, x256, x128, x64p, g };
    const int    hs[5]  = { 512, 256, 128, 64, 512 };

    for (int i = 0; i < 5; i++) {
        int H = hs[i], W = H;
        dim3 grid(W / 32, H / 8, 2);
        conv12_kernel<<<grid, 128>>>(
            sin[i], fWa + (size_t)i * 64 * 9, fba + i * 64,
            fWb + (size_t)i * 64 * 64 * 9, fbb + i * 64, h2, H, W);
        conv3x3_kernel<81, false><<<grid, 128>>>(
            h2, fWc + (size_t)i * 81 * 64 * 9, fbc + i * 81, fbuf, 64, H, W);
        int np = H * W;
        softmax_apply_kernel<<<dim3((np + 127) / 128, 2), 128>>>(
            fbuf, sin[i], cat, H, W, i, 512 / H);
    }

    dim3 gridF(512 / 32, 512 / 8, 2);
    conv3x3_kernel<64, true><<<gridF, 128>>>(cat, W2a, b2a, h1, 5, 512, 512);
    conv3x3_kernel<1, false><<<gridF, 128>>>(h1, W2b, b2b, out, 64, 512, 512);
}

// round 8
// speedup vs baseline: 1.2127x; 1.0702x over previous
#include <cuda_runtime.h>
#include <cstdint>

typedef unsigned long long ull;

// ---------------------------------------------------------------------------
// Scratch (device globals; no allocation anywhere)
// ---------------------------------------------------------------------------
__device__ float g_x256[2 * 256 * 256];
__device__ float g_x128[2 * 128 * 128];
__device__ float g_x64 [2 * 64 * 64];
__device__ float g_h1 [(size_t)2 * 64 * 512 * 512];
__device__ float g_h2 [(size_t)2 * 64 * 512 * 512];
__device__ float g_f  [(size_t)2 * 81 * 512 * 512];
__device__ float g_cat[(size_t)2 * 5  * 512 * 512];

// ---------------------------------------------------------------------------
// Packed f32x2 helpers (sm_103a FFMA2 path)
// ---------------------------------------------------------------------------
__device__ __forceinline__ void ffma2(ull& acc, ull a, ull b) {
    asm("fma.rn.f32x2 %0, %1, %2, %0;" : "+l"(acc) : "l"(a), "l"(b));
}
__device__ __forceinline__ ull packdup(float v) {
    ull r;
    asm("mov.b64 %0, {%1, %1};" : "=l"(r) : "f"(v));
    return r;
}
__device__ __forceinline__ ull pack2(float lo, float hi) {
    ull r;
    asm("mov.b64 %0, {%1, %2};" : "=l"(r) : "f"(lo), "f"(hi));
    return r;
}
__device__ __forceinline__ void unpack2(ull v, float& lo, float& hi) {
    asm("mov.b64 {%0, %1}, %2;" : "=f"(lo), "=f"(hi) : "l"(v));
}

// ---------------------------------------------------------------------------
// Nearest-neighbor downsample
// ---------------------------------------------------------------------------
__global__ void downsample_kernel(const float* __restrict__ in, float* __restrict__ out,
                                  int OH, int OW, int stride)
{
    int idx = blockIdx.x * blockDim.x + threadIdx.x;
    int n = blockIdx.y;
    if (idx >= OH * OW) return;
    int oy = idx / OW, ox = idx - oy * OW;
    out[(size_t)n * OH * OW + idx] =
        in[(size_t)n * 512 * 512 + (size_t)(oy * stride) * 512 + ox * stride];
}

// ---------------------------------------------------------------------------
// Direct 3x3 SAME conv, packed-f32x2 math, output-channel split ACROSS
// THREADS (coh). 128 threads; tile 32x8. For COUT>=64: thread =
// (px 0..7 -> 4 pixels, ty 0..7, coh 0..1); each thread owns GP pairs of its
// co-half. Patch smem channel-pair interleaved (float2 = channels 2s,2s+1);
// consume reads per-channel halves via LDS.32. Double-buffered, 2 input
// channels per barrier stage, global->reg prefetch overlapping compute.
// ---------------------------------------------------------------------------
template<int COUT, bool RELU>
__global__ __launch_bounds__(128, 3)
void conv3x3_kernel(const float* __restrict__ in, const float* __restrict__ wt,
                    const float* __restrict__ bias, float* __restrict__ out,
                    int C, int H, int W)
{
    constexpr int COH = (COUT >= 64) ? 2 : 1;
    constexpr int GP  = (COUT == 81) ? 7 : (COUT >= 64 ? 8 : (COUT + 1) / 2);
    constexpr int PXW = (COH == 2) ? 4 : 2;       // pixels per thread
    constexpr int NPAIR = (COUT + 1) / 2;
    constexpr int NG = (NPAIR + COH * GP - 1) / (COH * GP);
    constexpr int PS = 35, ROWS = 10;
    constexpr int PELEM = ROWS * PS;              // 350
    constexpr int WELEM = COH * GP * 18;
    constexpr int WITER = (WELEM + 127) / 128;

    __shared__ float2 patch2[2][PELEM];
    __shared__ __align__(16) float ws[2][2][COH * GP * 20];

    const int t   = threadIdx.x;
    const int px  = (COH == 2) ? (t & 7) : (t & 15);
    const int ty  = (COH == 2) ? ((t >> 3) & 7) : (t >> 4);
    const int coh = (COH == 2) ? (t >> 6) : 0;
    const int x0 = blockIdx.x << 5;
    const int y0 = blockIdx.y << 3;
    const int n  = blockIdx.z;
    const size_t HW = (size_t)H * W;
    const int NS = (C + 1) / 2;

    const float* inn = in + (size_t)n * C * HW;

    float pv[2][3];
    float pw[2][WITER];

    auto prefetch = [&](int g, int s) {
#pragma unroll
        for (int ch = 0; ch < 2; ch++) {
            int c = 2 * s + ch;
#pragma unroll
            for (int j = 0; j < 3; j++) {
                float v = 0.f;
                int e = t + j * 128;
                if (c < C && e < PELEM) {
                    int r = e / PS, cc = e - r * PS;
                    int gy = y0 + r - 1, gx = x0 + cc - 1;
                    if (cc < 34 && gy >= 0 && gy < H && gx >= 0 && gx < W)
                        v = inn[(size_t)c * HW + (size_t)gy * W + gx];
                }
                pv[ch][j] = v;
            }
#pragma unroll
            for (int j = 0; j < WITER; j++) {
                pw[ch][j] = 0.f;
                int e = t + j * 128;
                if (c < C && e < WELEM) {
                    int p2 = e / 18, r = e - p2 * 18;
                    int lane = r / 9, k = r - lane * 9;
                    int co = 2 * (g * COH * GP + p2) + lane;
                    if (co < COUT)
                        pw[ch][j] = wt[((size_t)co * C + c) * 9 + k];
                }
            }
        }
    };

    auto store_sm = [&](int b, int s) {
#pragma unroll
        for (int j = 0; j < 3; j++) {
            int e = t + j * 128;
            if (e < PELEM) patch2[b][e] = make_float2(pv[0][j], pv[1][j]);
        }
#pragma unroll
        for (int ch = 0; ch < 2; ch++)
#pragma unroll
            for (int j = 0; j < WITER; j++) {
                int e = t + j * 128;
                if (e < WELEM) {
                    int p2 = e / 18, r = e - p2 * 18;
                    int lane = r / 9, k = r - lane * 9;
                    ws[b][ch][p2 * 20 + 2 * k + lane] = pw[ch][j];
                }
            }
    };

#pragma unroll 1
    for (int g = 0; g < NG; ++g) {
        ull acc[GP][PXW];
#pragma unroll
        for (int p = 0; p < GP; p++)
#pragma unroll
            for (int q = 0; q < PXW; q++) acc[p][q] = 0ull;

        prefetch(g, 0);
#pragma unroll 1
        for (int s = 0; s < NS; ++s) {
            int b = s & 1;
            store_sm(b, s);
            __syncthreads();
            if (s + 1 < NS) prefetch(g, s + 1);

            const float* pbf = reinterpret_cast<const float*>(patch2[b]);
#pragma unroll
            for (int ch = 0; ch < 2; ch++) {
                if (2 * s + ch < C) {
                    ull dup[3][PXW + 2];
#pragma unroll
                    for (int ky = 0; ky < 3; ky++)
#pragma unroll
                        for (int j = 0; j < PXW + 2; j++)
                            dup[ky][j] = packdup(
                                pbf[2 * ((ty + ky) * PS + PXW * px + j) + ch]);

                    const float* wb = &ws[b][ch][coh * GP * 20];
#pragma unroll
                    for (int p = 0; p < GP; p++) {
                        ull w[9];
                        const ulonglong2* q2 = reinterpret_cast<const ulonglong2*>(wb + p * 20);
                        ulonglong2 q0 = q2[0], q1 = q2[1], qq = q2[2], q3 = q2[3];
                        w[0] = q0.x; w[1] = q0.y; w[2] = q1.x; w[3] = q1.y;
                        w[4] = qq.x; w[5] = qq.y; w[6] = q3.x; w[7] = q3.y;
                        w[8] = *reinterpret_cast<const ull*>(wb + p * 20 + 16);
#pragma unroll
                        for (int ky = 0; ky < 3; ky++)
#pragma unroll
                            for (int kx = 0; kx < 3; kx++)
#pragma unroll
                                for (int q = 0; q < PXW; q++)
                                    ffma2(acc[p][q], dup[ky][kx + q], w[ky * 3 + kx]);
                    }
                }
            }
        }

        {
            const int oy = y0 + ty;
            const int ox = x0 + PXW * px;
            float* outp = out + (size_t)n * COUT * HW + (size_t)oy * W + ox;
#pragma unroll
            for (int p = 0; p < GP; p++) {
                int co0 = 2 * (g * COH * GP + coh * GP + p);
                if (co0 < COUT) {
                    float lo[PXW], hi[PXW];
#pragma unroll
                    for (int q = 0; q < PXW; q++) unpack2(acc[p][q], lo[q], hi[q]);
                    float bi0 = __ldg(&bias[co0]);
                    float r[PXW];
#pragma unroll
                    for (int q = 0; q < PXW; q++) {
                        r[q] = lo[q] + bi0;
                        if (RELU) r[q] = fmaxf(r[q], 0.f);
                    }
                    if (PXW == 4)
                        *reinterpret_cast<float4*>(outp + (size_t)co0 * HW) =
                            make_float4(r[0], r[1], r[2], r[3]);
                    else
                        *reinterpret_cast<float2*>(outp + (size_t)co0 * HW) =
                            make_float2(r[0], r[1]);
                    if (co0 + 1 < COUT) {
                        float bi1 = __ldg(&bias[co0 + 1]);
                        float u[PXW];
#pragma unroll
                        for (int q = 0; q < PXW; q++) {
                            u[q] = hi[q] + bi1;
                            if (RELU) u[q] = fmaxf(u[q], 0.f);
                        }
                        if (PXW == 4)
                            *reinterpret_cast<float4*>(outp + (size_t)(co0 + 1) * HW) =
                                make_float4(u[0], u[1], u[2], u[3]);
                        else
                            *reinterpret_cast<float2*>(outp + (size_t)(co0 + 1) * HW) =
                                make_float2(u[0], u[1]);
                    }
                }
            }
        }
        __syncthreads();
    }
}

// ---------------------------------------------------------------------------
// Fused conv1(1->64,relu) + conv2(64->64,relu). Same co-split-across-threads
// consume structure (coh, GP=8 pairs, 4 px/thread). Conv1 recompute packed
// f32x2 over the stage's channel pair, weights hoisted per stage.
// ---------------------------------------------------------------------------
__global__ __launch_bounds__(128, 3)
void conv12_kernel(const float* __restrict__ x, const float* __restrict__ w1,
                   const float* __restrict__ b1, const float* __restrict__ w2,
                   const float* __restrict__ b2, float* __restrict__ out,
                   int H, int W)
{
    constexpr int GP = 8, NG = 2, COUT = 64;
    constexpr int PS = 35, ROWS = 10;
    constexpr int CELEM = ROWS * 34;            // 340 pair-positions
    constexpr int XPS = 37, XROWS = 12;
    constexpr int XELEM = XROWS * XPS;          // 444
    constexpr int WELEM = 2 * GP * 18;          // 288

    __shared__ float xpatch[XELEM];
    __shared__ ull w1pk[32 * 10];
    __shared__ float2 cbuf2[2][ROWS * PS];
    __shared__ __align__(16) float ws[2][2][2 * GP * 20];

    const int t   = threadIdx.x;
    const int px  = t & 7;
    const int ty  = (t >> 3) & 7;
    const int coh = t >> 6;
    const int x0 = blockIdx.x << 5;
    const int y0 = blockIdx.y << 3;
    const int n  = blockIdx.z;
    const size_t HW = (size_t)H * W;

    // one-time loads
    const float* xn = x + (size_t)n * HW;
#pragma unroll
    for (int j = 0; j < 4; j++) {
        int e = t + j * 128;
        if (e < XELEM) {
            int r = e / XPS, cc = e - r * XPS;
            int gy = y0 + r - 2, gx = x0 + cc - 2;
            float v = 0.f;
            if (cc < 36 && gy >= 0 && gy < H && gx >= 0 && gx < W)
                v = xn[(size_t)gy * W + gx];
            xpatch[e] = v;
        }
    }
#pragma unroll
    for (int j = 0; j < 3; j++) {
        int e = t + j * 128;
        if (e < 320) {
            int cp = e / 10, k = e - cp * 10;
            float lo, hi;
            if (k < 9) { lo = w1[(2 * cp) * 9 + k]; hi = w1[(2 * cp + 1) * 9 + k]; }
            else       { lo = b1[2 * cp];           hi = b1[2 * cp + 1]; }
            w1pk[e] = pack2(lo, hi);
        }
    }
    __syncthreads();

    float pw[2][3];
    auto prefetch_w = [&](int g, int s) {
#pragma unroll
        for (int ch = 0; ch < 2; ch++) {
            int c = 2 * s + ch;
#pragma unroll
            for (int j = 0; j < 3; j++) {
                pw[ch][j] = 0.f;
                int e = t + j * 128;
                if (e < WELEM) {
                    int p2 = e / 18, r = e - p2 * 18;
                    int lane = r / 9, k = r - lane * 9;
                    int co = 2 * (g * 16 + p2) + lane;
                    pw[ch][j] = w2[((size_t)co * 64 + c) * 9 + k];
                }
            }
        }
    };

#pragma unroll 1
    for (int g = 0; g < NG; ++g) {
        ull acc[GP][4];
#pragma unroll
        for (int p = 0; p < GP; p++)
#pragma unroll
            for (int q = 0; q < 4; q++) acc[p][q] = 0ull;

        prefetch_w(g, 0);
#pragma unroll 1
        for (int s = 0; s < 32; ++s) {
            int b = s & 1;

            // conv1 weights for channel pair s (broadcast, hoisted)
            ull w1r[10];
#pragma unroll
            for (int k = 0; k < 10; k++) w1r[k] = w1pk[s * 10 + k];

            // produce conv1 channels 2s,2s+1 packed over the 10x34 halo region
#pragma unroll
            for (int j = 0; j < 3; j++) {
                int e = t + j * 128;
                if (e < CELEM) {
                    int r = e / 34, col = e - r * 34;
                    int gy = y0 + r - 1, gx = x0 + col - 1;
                    float2 v = make_float2(0.f, 0.f);
                    if (gy >= 0 && gy < H && gx >= 0 && gx < W) {
                        ull a = w1r[9];
#pragma unroll
                        for (int dy = 0; dy < 3; dy++)
#pragma unroll
                            for (int dx = 0; dx < 3; dx++)
                                ffma2(a, packdup(xpatch[(r + dy) * XPS + col + dx]),
                                      w1r[dy * 3 + dx]);
                        float lo, hi;
                        unpack2(a, lo, hi);
                        v = make_float2(fmaxf(lo, 0.f), fmaxf(hi, 0.f));
                    }
                    cbuf2[b][r * PS + col] = v;
                }
            }
            // stage conv2 weights
#pragma unroll
            for (int ch = 0; ch < 2; ch++)
#pragma unroll
                for (int j = 0; j < 3; j++) {
                    int e = t + j * 128;
                    if (e < WELEM) {
                        int p2 = e / 18, r = e - p2 * 18;
                        int lane = r / 9, k = r - lane * 9;
                        ws[b][ch][p2 * 20 + 2 * k + lane] = pw[ch][j];
                    }
                }
            __syncthreads();
            if (s + 1 < 32) prefetch_w(g, s + 1);

            const float* pbf = reinterpret_cast<const float*>(cbuf2[b]);
#pragma unroll
            for (int ch = 0; ch < 2; ch++) {
                ull dup[3][6];
#pragma unroll
                for (int ky = 0; ky < 3; ky++)
#pragma unroll
                    for (int j = 0; j < 6; j++)
                        dup[ky][j] = packdup(
                            pbf[2 * ((ty + ky) * PS + 4 * px + j) + ch]);

                const float* wb = &ws[b][ch][coh * GP * 20];
#pragma unroll
                for (int p = 0; p < GP; p++) {
                    ull w[9];
                    const ulonglong2* q2 = reinterpret_cast<const ulonglong2*>(wb + p * 20);
                    ulonglong2 q0 = q2[0], q1 = q2[1], qq = q2[2], q3 = q2[3];
                    w[0] = q0.x; w[1] = q0.y; w[2] = q1.x; w[3] = q1.y;
                    w[4] = qq.x; w[5] = qq.y; w[6] = q3.x; w[7] = q3.y;
                    w[8] = *reinterpret_cast<const ull*>(wb + p * 20 + 16);
#pragma unroll
                    for (int ky = 0; ky < 3; ky++)
#pragma unroll
                        for (int kx = 0; kx < 3; kx++)
#pragma unroll
                            for (int q = 0; q < 4; q++)
                                ffma2(acc[p][q], dup[ky][kx + q], w[ky * 3 + kx]);
                }
            }
        }

        {
            const int oy = y0 + ty;
            const int ox = x0 + 4 * px;
            float* outp = out + (size_t)n * COUT * HW + (size_t)oy * W + ox;
#pragma unroll
            for (int p = 0; p < GP; p++) {
                int co0 = 2 * (g * 16 + coh * GP + p);
                float lo[4], hi[4];
#pragma unroll
                for (int q = 0; q < 4; q++) unpack2(acc[p][q], lo[q], hi[q]);
                float bi0 = __ldg(&b2[co0]);
                float bi1 = __ldg(&b2[co0 + 1]);
                float4 r0 = make_float4(fmaxf(lo[0] + bi0, 0.f), fmaxf(lo[1] + bi0, 0.f),
                                        fmaxf(lo[2] + bi0, 0.f), fmaxf(lo[3] + bi0, 0.f));
                float4 r1 = make_float4(fmaxf(hi[0] + bi1, 0.f), fmaxf(hi[1] + bi1, 0.f),
                                        fmaxf(hi[2] + bi1, 0.f), fmaxf(hi[3] + bi1, 0.f));
                *reinterpret_cast<float4*>(outp + (size_t)co0 * HW) = r0;
                *reinterpret_cast<float4*>(outp + (size_t)(co0 + 1) * HW) = r1;
            }
        }
        __syncthreads();
    }
}

// ---------------------------------------------------------------------------
// Softmax(81) + 9x9 dynamic conv + nearest upsample into concat channel
// ---------------------------------------------------------------------------
__global__ __launch_bounds__(128)
void softmax_apply_kernel(const float* __restrict__ f, const float* __restrict__ s,
                          float* __restrict__ cat, int H, int W, int ch, int factor)
{
    int idx = blockIdx.x * blockDim.x + threadIdx.x;
    int n = blockIdx.y;
    if (idx >= H * W) return;
    int iy = idx / W, ix = idx - iy * W;

    const float* fn = f + (size_t)n * 81 * H * W + idx;
    float lg[81];
    float mx = -1e30f;
#pragma unroll
    for (int k = 0; k < 81; k++) {
        lg[k] = fn[(size_t)k * H * W];
        mx = fmaxf(mx, lg[k]);
    }
    float sum = 0.f;
#pragma unroll
    for (int k = 0; k < 81; k++) {
        lg[k] = __expf(lg[k] - mx);
        sum += lg[k];
    }
    float inv = 1.f / sum;

    const float* sn = s + (size_t)n * H * W;
    float outv = 0.f;
#pragma unroll
    for (int dy = 0; dy < 9; dy++) {
        int yy = iy + dy - 4;
#pragma unroll
        for (int dx = 0; dx < 9; dx++) {
            int xx = ix + dx - 4;
            float xv = (yy >= 0 && yy < H && xx >= 0 && xx < W)
                         ? sn[(size_t)yy * W + xx] : 0.f;
            outv += lg[dy * 9 + dx] * xv;
        }
    }
    outv *= inv;

    float* cn = cat + ((size_t)n * 5 + ch) * 512 * 512;
    int oy0 = iy * factor, ox0 = ix * factor;
    for (int ry = 0; ry < factor; ry++)
        for (int rx = 0; rx < factor; rx++)
            cn[(size_t)(oy0 + ry) * 512 + ox0 + rx] = outv;
}

// ---------------------------------------------------------------------------
// Launch
// ---------------------------------------------------------------------------
extern "C" void kernel_launch(void* const* d_in, const int* in_sizes, int n_in,
                              void* d_out, int out_size)
{
    const float* x   = (const float*)d_in[0];
    const float* g   = (const float*)d_in[1];
    const float* fWa = (const float*)d_in[2];
    const float* fba = (const float*)d_in[3];
    const float* fWb = (const float*)d_in[4];
    const float* fbb = (const float*)d_in[5];
    const float* fWc = (const float*)d_in[6];
    const float* fbc = (const float*)d_in[7];
    const float* W2a = (const float*)d_in[8];
    const float* b2a = (const float*)d_in[9];
    const float* W2b = (const float*)d_in[10];
    const float* b2b = (const float*)d_in[11];
    float* out = (float*)d_out;

    float *x256, *x128, *x64p, *h1, *h2, *fbuf, *cat;
    cudaGetSymbolAddress((void**)&x256, g_x256);
    cudaGetSymbolAddress((void**)&x128, g_x128);
    cudaGetSymbolAddress((void**)&x64p, g_x64);
    cudaGetSymbolAddress((void**)&h1,   g_h1);
    cudaGetSymbolAddress((void**)&h2,   g_h2);
    cudaGetSymbolAddress((void**)&fbuf, g_f);
    cudaGetSymbolAddress((void**)&cat,  g_cat);

    downsample_kernel<<<dim3((256 * 256 + 255) / 256, 2), 256>>>(x, x256, 256, 256, 2);
    downsample_kernel<<<dim3((128 * 128 + 255) / 256, 2), 256>>>(x, x128, 128, 128, 4);
    downsample_kernel<<<dim3((64 * 64 + 255) / 256, 2), 256>>>(x, x64p, 64, 64, 8);

    const float* sin[5] = { x, x256, x128, x64p, g };
    const int    hs[5]  = { 512, 256, 128, 64, 512 };

    for (int i = 0; i < 5; i++) {
        int H = hs[i], W = H;
        dim3 grid(W / 32, H / 8, 2);
        conv12_kernel<<<grid, 128>>>(
            sin[i], fWa + (size_t)i * 64 * 9, fba + i * 64,
            fWb + (size_t)i * 64 * 64 * 9, fbb + i * 64, h2, H, W);
        conv3x3_kernel<81, false><<<grid, 128>>>(
            h2, fWc + (size_t)i * 81 * 64 * 9, fbc + i * 81, fbuf, 64, H, W);
        int np = H * W;
        softmax_apply_kernel<<<dim3((np + 127) / 128, 2), 128>>>(
            fbuf, sin[i], cat, H, W, i, 512 / H);
    }

    dim3 gridF(512 / 32, 512 / 8, 2);
    conv3x3_kernel<64, true><<<gridF, 128>>>(cat, W2a, b2a, h1, 5, 512, 512);
    conv3x3_kernel<1, false><<<gridF, 128>>>(h1, W2b, b2b, out, 64, 512, 512);
}

// round 10
// speedup vs baseline: 1.3622x; 1.1233x over previous
#include <cuda_runtime.h>
#include <cstdint>

typedef unsigned long long ull;

// ---------------------------------------------------------------------------
// Scale tables. Scale order (big first for launch packing):
//   s=0: x @512 (widx 0, cat ch 0, stride 1)
//   s=1: g @512 (widx 4, cat ch 4, stride 1)
//   s=2: x @256 (widx 1, cat ch 1, stride 2)
//   s=3: x @128 (widx 2, cat ch 2, stride 4)
//   s=4: x @64  (widx 3, cat ch 3, stride 8)
// ---------------------------------------------------------------------------
__constant__ int   c_H[5]      = {512, 512, 256, 128, 64};
__constant__ int   c_stride[5] = {1, 1, 2, 4, 8};
__constant__ int   c_widx[5]   = {0, 4, 1, 2, 3};
__constant__ int   c_isg[5]    = {0, 1, 0, 0, 0};
// conv block offsets: blocks = (W/32)*(H/8)*2
__constant__ int   c_cboff[6]  = {0, 2048, 4096, 4608, 4736, 4768};
// softmax block offsets: blocks = ceil(HW/128)*2
__constant__ int   c_sboff[6]  = {0, 4096, 8192, 9216, 9472, 9536};
// element offsets (floats) of per-scale regions in h2 (2*64*HW each)
__constant__ size_t c_h2off[5] = {0ull, 33554432ull, 67108864ull, 75497472ull, 77594624ull};
// element offsets in f (2*81*HW each)
__constant__ size_t c_foff[5]  = {0ull, 42467328ull, 84934656ull, 95551488ull, 98205696ull};

// ---------------------------------------------------------------------------
// Scratch (device globals; no allocation anywhere)
// ---------------------------------------------------------------------------
__device__ float g_h1 [(size_t)2 * 64 * 512 * 512];             // final conv intermediate
__device__ float g_h2 [78118912];                                // all scales, conv2 out
__device__ float g_f  [98869248];                                // all scales, conv3 logits
__device__ float g_cat[(size_t)2 * 5 * 512 * 512];               // concat buffer

// ---------------------------------------------------------------------------
// Packed f32x2 helpers (sm_103a FFMA2 path)
// ---------------------------------------------------------------------------
__device__ __forceinline__ void ffma2(ull& acc, ull a, ull b) {
    asm("fma.rn.f32x2 %0, %1, %2, %0;" : "+l"(acc) : "l"(a), "l"(b));
}
__device__ __forceinline__ ull packdup(float v) {
    ull r;
    asm("mov.b64 %0, {%1, %1};" : "=l"(r) : "f"(v));
    return r;
}
__device__ __forceinline__ ull pack2(float lo, float hi) {
    ull r;
    asm("mov.b64 %0, {%1, %2};" : "=l"(r) : "f"(lo), "f"(hi));
    return r;
}
__device__ __forceinline__ void unpack2(ull v, float& lo, float& hi) {
    asm("mov.b64 {%0, %1}, %2;" : "=f"(lo), "=f"(hi) : "l"(v));
}

// ---------------------------------------------------------------------------
// Fused conv1(1->64,relu) + conv2(64->64,relu), ALL SCALES in one launch.
// Per-block scale decode from constant tables. Input read directly from the
// full-res source with nearest-neighbor stride (no downsample buffers).
// Inner loops identical to R8: co split across threads (coh), GP=8 pairs,
// 4 px/thread, packed-f32x2 conv1 recompute, double-buffered stages.
// ---------------------------------------------------------------------------
__global__ __launch_bounds__(128, 3)
void conv12_all_kernel(const float* __restrict__ x, const float* __restrict__ g,
                       const float* __restrict__ fWa, const float* __restrict__ fba,
                       const float* __restrict__ fWb, const float* __restrict__ fbb,
                       float* __restrict__ h2)
{
    constexpr int GP = 8, NG = 2, COUT = 64;
    constexpr int PS = 35, ROWS = 10;
    constexpr int CELEM = ROWS * 34;
    constexpr int XPS = 37, XROWS = 12;
    constexpr int XELEM = XROWS * XPS;
    constexpr int WELEM = 2 * GP * 18;

    __shared__ float xpatch[XELEM];
    __shared__ ull w1pk[32 * 10];
    __shared__ float2 cbuf2[2][ROWS * PS];
    __shared__ __align__(16) float ws[2][2][2 * GP * 20];

    // ---- scale decode ----
    int bid = blockIdx.x;
    int sc;
    if      (bid < c_cboff[1]) sc = 0;
    else if (bid < c_cboff[2]) sc = 1;
    else if (bid < c_cboff[3]) sc = 2;
    else if (bid < c_cboff[4]) sc = 3;
    else                       sc = 4;
    int rem = bid - c_cboff[sc];
    const int H = c_H[sc], W = H;
    const int stride = c_stride[sc];
    const int bw = W >> 5, bh = H >> 3;
    const int n = rem / (bw * bh);  rem -= n * bw * bh;
    const int by = rem / bw, bx = rem - by * bw;
    const int widx = c_widx[sc];
    const float* src = (c_isg[sc] ? g : x) + (size_t)n * 512 * 512;
    const float* w1 = fWa + (size_t)widx * 64 * 9;
    const float* b1 = fba + widx * 64;
    const float* w2 = fWb + (size_t)widx * 64 * 64 * 9;
    const float* b2 = fbb + widx * 64;
    float* out = h2 + c_h2off[sc];

    const int t   = threadIdx.x;
    const int px  = t & 7;
    const int ty  = (t >> 3) & 7;
    const int coh = t >> 6;
    const int x0 = bx << 5;
    const int y0 = by << 3;
    const size_t HW = (size_t)H * W;

    // one-time loads (strided nearest-neighbor read of the source)
#pragma unroll
    for (int j = 0; j < 4; j++) {
        int e = t + j * 128;
        if (e < XELEM) {
            int r = e / XPS, cc = e - r * XPS;
            int gy = y0 + r - 2, gx = x0 + cc - 2;
            float v = 0.f;
            if (cc < 36 && gy >= 0 && gy < H && gx >= 0 && gx < W)
                v = src[(size_t)(gy * stride) * 512 + gx * stride];
            xpatch[e] = v;
        }
    }
#pragma unroll
    for (int j = 0; j < 3; j++) {
        int e = t + j * 128;
        if (e < 320) {
            int cp = e / 10, k = e - cp * 10;
            float lo, hi;
            if (k < 9) { lo = w1[(2 * cp) * 9 + k]; hi = w1[(2 * cp + 1) * 9 + k]; }
            else       { lo = b1[2 * cp];           hi = b1[2 * cp + 1]; }
            w1pk[e] = pack2(lo, hi);
        }
    }
    __syncthreads();

    float pw[2][3];
    auto prefetch_w = [&](int g2, int s) {
#pragma unroll
        for (int ch = 0; ch < 2; ch++) {
            int c = 2 * s + ch;
#pragma unroll
            for (int j = 0; j < 3; j++) {
                pw[ch][j] = 0.f;
                int e = t + j * 128;
                if (e < WELEM) {
                    int p2 = e / 18, r = e - p2 * 18;
                    int lane = r / 9, k = r - lane * 9;
                    int co = 2 * (g2 * 16 + p2) + lane;
                    pw[ch][j] = w2[((size_t)co * 64 + c) * 9 + k];
                }
            }
        }
    };

#pragma unroll 1
    for (int g2 = 0; g2 < NG; ++g2) {
        ull acc[GP][4];
#pragma unroll
        for (int p = 0; p < GP; p++)
#pragma unroll
            for (int q = 0; q < 4; q++) acc[p][q] = 0ull;

        prefetch_w(g2, 0);
#pragma unroll 1
        for (int s = 0; s < 32; ++s) {
            int b = s & 1;

            ull w1r[10];
#pragma unroll
            for (int k = 0; k < 10; k++) w1r[k] = w1pk[s * 10 + k];

#pragma unroll
            for (int j = 0; j < 3; j++) {
                int e = t + j * 128;
                if (e < CELEM) {
                    int r = e / 34, col = e - r * 34;
                    int gy = y0 + r - 1, gx = x0 + col - 1;
                    float2 v = make_float2(0.f, 0.f);
                    if (gy >= 0 && gy < H && gx >= 0 && gx < W) {
                        ull a = w1r[9];
#pragma unroll
                        for (int dy = 0; dy < 3; dy++)
#pragma unroll
                            for (int dx = 0; dx < 3; dx++)
                                ffma2(a, packdup(xpatch[(r + dy) * XPS + col + dx]),
                                      w1r[dy * 3 + dx]);
                        float lo, hi;
                        unpack2(a, lo, hi);
                        v = make_float2(fmaxf(lo, 0.f), fmaxf(hi, 0.f));
                    }
                    cbuf2[b][r * PS + col] = v;
                }
            }
#pragma unroll
            for (int ch = 0; ch < 2; ch++)
#pragma unroll
                for (int j = 0; j < 3; j++) {
                    int e = t + j * 128;
                    if (e < WELEM) {
                        int p2 = e / 18, r = e - p2 * 18;
                        int lane = r / 9, k = r - lane * 9;
                        ws[b][ch][p2 * 20 + 2 * k + lane] = pw[ch][j];
                    }
                }
            __syncthreads();
            if (s + 1 < 32) prefetch_w(g2, s + 1);

            const float* pbf = reinterpret_cast<const float*>(cbuf2[b]);
#pragma unroll
            for (int ch = 0; ch < 2; ch++) {
                ull dup[3][6];
#pragma unroll
                for (int ky = 0; ky < 3; ky++)
#pragma unroll
                    for (int j = 0; j < 6; j++)
                        dup[ky][j] = packdup(
                            pbf[2 * ((ty + ky) * PS + 4 * px + j) + ch]);

                const float* wb = &ws[b][ch][coh * GP * 20];
#pragma unroll
                for (int p = 0; p < GP; p++) {
                    ull w[9];
                    const ulonglong2* q2 = reinterpret_cast<const ulonglong2*>(wb + p * 20);
                    ulonglong2 q0 = q2[0], q1 = q2[1], qq = q2[2], q3 = q2[3];
                    w[0] = q0.x; w[1] = q0.y; w[2] = q1.x; w[3] = q1.y;
                    w[4] = qq.x; w[5] = qq.y; w[6] = q3.x; w[7] = q3.y;
                    w[8] = *reinterpret_cast<const ull*>(wb + p * 20 + 16);
#pragma unroll
                    for (int ky = 0; ky < 3; ky++)
#pragma unroll
                        for (int kx = 0; kx < 3; kx++)
#pragma unroll
                            for (int q = 0; q < 4; q++)
                                ffma2(acc[p][q], dup[ky][kx + q], w[ky * 3 + kx]);
                }
            }
        }

        {
            const int oy = y0 + ty;
            const int ox = x0 + 4 * px;
            float* outp = out + ((size_t)n * COUT) * HW + (size_t)oy * W + ox;
#pragma unroll
            for (int p = 0; p < GP; p++) {
                int co0 = 2 * (g2 * 16 + coh * GP + p);
                float lo[4], hi[4];
#pragma unroll
                for (int q = 0; q < 4; q++) unpack2(acc[p][q], lo[q], hi[q]);
                float bi0 = __ldg(&b2[co0]);
                float bi1 = __ldg(&b2[co0 + 1]);
                float4 r0 = make_float4(fmaxf(lo[0] + bi0, 0.f), fmaxf(lo[1] + bi0, 0.f),
                                        fmaxf(lo[2] + bi0, 0.f), fmaxf(lo[3] + bi0, 0.f));
                float4 r1 = make_float4(fmaxf(hi[0] + bi1, 0.f), fmaxf(hi[1] + bi1, 0.f),
                                        fmaxf(hi[2] + bi1, 0.f), fmaxf(hi[3] + bi1, 0.f));
                *reinterpret_cast<float4*>(outp + (size_t)co0 * HW) = r0;
                *reinterpret_cast<float4*>(outp + (size_t)(co0 + 1) * HW) = r1;
            }
        }
        __syncthreads();
    }
}

// ---------------------------------------------------------------------------
// conv3 (64 -> 81 logits), ALL SCALES in one launch. Inner structure = R8
// conv3x3<81>: COH=2 co-halves across threads, GP=7 pairs, 4 px/thread, NG=3.
// ---------------------------------------------------------------------------
__global__ __launch_bounds__(128, 3)
void conv81_all_kernel(const float* __restrict__ h2, const float* __restrict__ fWc,
                       const float* __restrict__ fbc, float* __restrict__ f)
{
    constexpr int COUT = 81, C = 64;
    constexpr int COH = 2, GP = 7, PXW = 4;
    constexpr int NG = 3;
    constexpr int PS = 35, ROWS = 10;
    constexpr int PELEM = ROWS * PS;
    constexpr int WELEM = COH * GP * 18;   // 252
    constexpr int WITER = 2;

    __shared__ float2 patch2[2][PELEM];
    __shared__ __align__(16) float ws[2][2][COH * GP * 20];

    // ---- scale decode ----
    int bid = blockIdx.x;
    int sc;
    if      (bid < c_cboff[1]) sc = 0;
    else if (bid < c_cboff[2]) sc = 1;
    else if (bid < c_cboff[3]) sc = 2;
    else if (bid < c_cboff[4]) sc = 3;
    else                       sc = 4;
    int rem = bid - c_cboff[sc];
    const int H = c_H[sc], W = H;
    const int bw = W >> 5, bh = H >> 3;
    const int n = rem / (bw * bh);  rem -= n * bw * bh;
    const int by = rem / bw, bx = rem - by * bw;
    const int widx = c_widx[sc];
    const float* wt = fWc + (size_t)widx * 81 * 64 * 9;
    const float* bias = fbc + widx * 81;
    const size_t HW = (size_t)H * W;
    const float* inn = h2 + c_h2off[sc] + (size_t)n * C * HW;
    float* out = f + c_foff[sc] + (size_t)n * COUT * HW;

    const int t   = threadIdx.x;
    const int px  = t & 7;
    const int ty  = (t >> 3) & 7;
    const int coh = t >> 6;
    const int x0 = bx << 5;
    const int y0 = by << 3;
    const int NS = 32;

    float pv[2][3];
    float pw[2][WITER];

    auto prefetch = [&](int g2, int s) {
#pragma unroll
        for (int ch = 0; ch < 2; ch++) {
            int c = 2 * s + ch;
#pragma unroll
            for (int j = 0; j < 3; j++) {
                float v = 0.f;
                int e = t + j * 128;
                if (e < PELEM) {
                    int r = e / PS, cc = e - r * PS;
                    int gy = y0 + r - 1, gx = x0 + cc - 1;
                    if (cc < 34 && gy >= 0 && gy < H && gx >= 0 && gx < W)
                        v = inn[(size_t)c * HW + (size_t)gy * W + gx];
                }
                pv[ch][j] = v;
            }
#pragma unroll
            for (int j = 0; j < WITER; j++) {
                pw[ch][j] = 0.f;
                int e = t + j * 128;
                if (e < WELEM) {
                    int p2 = e / 18, r = e - p2 * 18;
                    int lane = r / 9, k = r - lane * 9;
                    int co = 2 * (g2 * COH * GP + p2) + lane;
                    if (co < COUT)
                        pw[ch][j] = wt[((size_t)co * C + c) * 9 + k];
                }
            }
        }
    };

    auto store_sm = [&](int b) {
#pragma unroll
        for (int j = 0; j < 3; j++) {
            int e = t + j * 128;
            if (e < PELEM) patch2[b][e] = make_float2(pv[0][j], pv[1][j]);
        }
#pragma unroll
        for (int ch = 0; ch < 2; ch++)
#pragma unroll
            for (int j = 0; j < WITER; j++) {
                int e = t + j * 128;
                if (e < WELEM) {
                    int p2 = e / 18, r = e - p2 * 18;
                    int lane = r / 9, k = r - lane * 9;
                    ws[b][ch][p2 * 20 + 2 * k + lane] = pw[ch][j];
                }
            }
    };

#pragma unroll 1
    for (int g2 = 0; g2 < NG; ++g2) {
        ull acc[GP][PXW];
#pragma unroll
        for (int p = 0; p < GP; p++)
#pragma unroll
            for (int q = 0; q < PXW; q++) acc[p][q] = 0ull;

        prefetch(g2, 0);
#pragma unroll 1
        for (int s = 0; s < NS; ++s) {
            int b = s & 1;
            store_sm(b);
            __syncthreads();
            if (s + 1 < NS) prefetch(g2, s + 1);

            const float* pbf = reinterpret_cast<const float*>(patch2[b]);
#pragma unroll
            for (int ch = 0; ch < 2; ch++) {
                ull dup[3][PXW + 2];
#pragma unroll
                for (int ky = 0; ky < 3; ky++)
#pragma unroll
                    for (int j = 0; j < PXW + 2; j++)
                        dup[ky][j] = packdup(
                            pbf[2 * ((ty + ky) * PS + PXW * px + j) + ch]);

                const float* wb = &ws[b][ch][coh * GP * 20];
#pragma unroll
                for (int p = 0; p < GP; p++) {
                    ull w[9];
                    const ulonglong2* q2 = reinterpret_cast<const ulonglong2*>(wb + p * 20);
                    ulonglong2 q0 = q2[0], q1 = q2[1], qq = q2[2], q3 = q2[3];
                    w[0] = q0.x; w[1] = q0.y; w[2] = q1.x; w[3] = q1.y;
                    w[4] = qq.x; w[5] = qq.y; w[6] = q3.x; w[7] = q3.y;
                    w[8] = *reinterpret_cast<const ull*>(wb + p * 20 + 16);
#pragma unroll
                    for (int ky = 0; ky < 3; ky++)
#pragma unroll
                        for (int kx = 0; kx < 3; kx++)
#pragma unroll
                            for (int q = 0; q < PXW; q++)
                                ffma2(acc[p][q], dup[ky][kx + q], w[ky * 3 + kx]);
                }
            }
        }

        {
            const int oy = y0 + ty;
            const int ox = x0 + PXW * px;
            float* outp = out + (size_t)oy * W + ox;
#pragma unroll
            for (int p = 0; p < GP; p++) {
                int co0 = 2 * (g2 * COH * GP + coh * GP + p);
                if (co0 < COUT) {
                    float lo[PXW], hi[PXW];
#pragma unroll
                    for (int q = 0; q < PXW; q++) unpack2(acc[p][q], lo[q], hi[q]);
                    float bi0 = __ldg(&bias[co0]);
                    float4 r0 = make_float4(lo[0] + bi0, lo[1] + bi0,
                                            lo[2] + bi0, lo[3] + bi0);
                    *reinterpret_cast<float4*>(outp + (size_t)co0 * HW) = r0;
                    if (co0 + 1 < COUT) {
                        float bi1 = __ldg(&bias[co0 + 1]);
                        float4 r1 = make_float4(hi[0] + bi1, hi[1] + bi1,
                                                hi[2] + bi1, hi[3] + bi1);
                        *reinterpret_cast<float4*>(outp + (size_t)(co0 + 1) * HW) = r1;
                    }
                }
            }
        }
        __syncthreads();
    }
}

// ---------------------------------------------------------------------------
// Softmax(81) + 9x9 dynamic conv + nearest upsample into concat channel,
// ALL SCALES in one launch. Dyn-conv input read from full-res source with
// nearest stride.
// ---------------------------------------------------------------------------
__global__ __launch_bounds__(128)
void softmax_all_kernel(const float* __restrict__ f, const float* __restrict__ x,
                        const float* __restrict__ g, float* __restrict__ cat)
{
    int bid = blockIdx.x;
    int sc;
    if      (bid < c_sboff[1]) sc = 0;
    else if (bid < c_sboff[2]) sc = 1;
    else if (bid < c_sboff[3]) sc = 2;
    else if (bid < c_sboff[4]) sc = 3;
    else                       sc = 4;
    int rem = bid - c_sboff[sc];
    const int H = c_H[sc], W = H;
    const int stride = c_stride[sc];
    const int nbp = (H * W + 127) / 128;          // blocks per batch
    const int n = rem / nbp;
    const int idx = (rem - n * nbp) * 128 + threadIdx.x;
    if (idx >= H * W) return;
    const int iy = idx / W, ix = idx - iy * W;
    const int ch = c_widx[sc];                    // cat channel == weight index
    const int factor = 512 / H;

    const float* fn = f + c_foff[sc] + (size_t)n * 81 * H * W + idx;
    float lg[81];
    float mx = -1e30f;
#pragma unroll
    for (int k = 0; k < 81; k++) {
        lg[k] = fn[(size_t)k * H * W];
        mx = fmaxf(mx, lg[k]);
    }
    float sum = 0.f;
#pragma unroll
    for (int k = 0; k < 81; k++) {
        lg[k] = __expf(lg[k] - mx);
        sum += lg[k];
    }
    float inv = 1.f / sum;

    const float* sn = (c_isg[sc] ? g : x) + (size_t)n * 512 * 512;
    float outv = 0.f;
#pragma unroll
    for (int dy = 0; dy < 9; dy++) {
        int yy = iy + dy - 4;
#pragma unroll
        for (int dx = 0; dx < 9; dx++) {
            int xx = ix + dx - 4;
            float xv = (yy >= 0 && yy < H && xx >= 0 && xx < W)
                         ? sn[(size_t)(yy * stride) * 512 + xx * stride] : 0.f;
            outv += lg[dy * 9 + dx] * xv;
        }
    }
    outv *= inv;

    float* cn = cat + ((size_t)n * 5 + ch) * 512 * 512;
    int oy0 = iy * factor, ox0 = ix * factor;
    for (int ry = 0; ry < factor; ry++)
        for (int rx = 0; rx < factor; rx++)
            cn[(size_t)(oy0 + ry) * 512 + ox0 + rx] = outv;
}

// ---------------------------------------------------------------------------
// Generic direct 3x3 SAME conv (for the final 5->64 and 64->1 convs).
// Identical to R8 conv3x3_kernel.
// ---------------------------------------------------------------------------
template<int COUT, bool RELU>
__global__ __launch_bounds__(128, 3)
void conv3x3_kernel(const float* __restrict__ in, const float* __restrict__ wt,
                    const float* __restrict__ bias, float* __restrict__ out,
                    int C, int H, int W)
{
    constexpr int COH = (COUT >= 64) ? 2 : 1;
    constexpr int GP  = (COUT == 81) ? 7 : (COUT >= 64 ? 8 : (COUT + 1) / 2);
    constexpr int PXW = (COH == 2) ? 4 : 2;
    constexpr int NPAIR = (COUT + 1) / 2;
    constexpr int NG = (NPAIR + COH * GP - 1) / (COH * GP);
    constexpr int PS = 35, ROWS = 10;
    constexpr int PELEM = ROWS * PS;
    constexpr int WELEM = COH * GP * 18;
    constexpr int WITER = (WELEM + 127) / 128;

    __shared__ float2 patch2[2][PELEM];
    __shared__ __align__(16) float ws[2][2][COH * GP * 20];

    const int t   = threadIdx.x;
    const int px  = (COH == 2) ? (t & 7) : (t & 15);
    const int ty  = (COH == 2) ? ((t >> 3) & 7) : (t >> 4);
    const int coh = (COH == 2) ? (t >> 6) : 0;
    const int x0 = blockIdx.x << 5;
    const int y0 = blockIdx.y << 3;
    const int n  = blockIdx.z;
    const size_t HW = (size_t)H * W;
    const int NS = (C + 1) / 2;

    const float* inn = in + (size_t)n * C * HW;

    float pv[2][3];
    float pw[2][WITER];

    auto prefetch = [&](int g, int s) {
#pragma unroll
        for (int ch = 0; ch < 2; ch++) {
            int c = 2 * s + ch;
#pragma unroll
            for (int j = 0; j < 3; j++) {
                float v = 0.f;
                int e = t + j * 128;
                if (c < C && e < PELEM) {
                    int r = e / PS, cc = e - r * PS;
                    int gy = y0 + r - 1, gx = x0 + cc - 1;
                    if (cc < 34 && gy >= 0 && gy < H && gx >= 0 && gx < W)
                        v = inn[(size_t)c * HW + (size_t)gy * W + gx];
                }
                pv[ch][j] = v;
            }
#pragma unroll
            for (int j = 0; j < WITER; j++) {
                pw[ch][j] = 0.f;
                int e = t + j * 128;
                if (c < C && e < WELEM) {
                    int p2 = e / 18, r = e - p2 * 18;
                    int lane = r / 9, k = r - lane * 9;
                    int co = 2 * (g * COH * GP + p2) + lane;
                    if (co < COUT)
                        pw[ch][j] = wt[((size_t)co * C + c) * 9 + k];
                }
            }
        }
    };

    auto store_sm = [&](int b, int s) {
#pragma unroll
        for (int j = 0; j < 3; j++) {
            int e = t + j * 128;
            if (e < PELEM) patch2[b][e] = make_float2(pv[0][j], pv[1][j]);
        }
#pragma unroll
        for (int ch = 0; ch < 2; ch++)
#pragma unroll
            for (int j = 0; j < WITER; j++) {
                int e = t + j * 128;
                if (e < WELEM) {
                    int p2 = e / 18, r = e - p2 * 18;
                    int lane = r / 9, k = r - lane * 9;
                    ws[b][ch][p2 * 20 + 2 * k + lane] = pw[ch][j];
                }
            }
    };

#pragma unroll 1
    for (int g = 0; g < NG; ++g) {
        ull acc[GP][PXW];
#pragma unroll
        for (int p = 0; p < GP; p++)
#pragma unroll
            for (int q = 0; q < PXW; q++) acc[p][q] = 0ull;

        prefetch(g, 0);
#pragma unroll 1
        for (int s = 0; s < NS; ++s) {
            int b = s & 1;
            store_sm(b, s);
            __syncthreads();
            if (s + 1 < NS) prefetch(g, s + 1);

            const float* pbf = reinterpret_cast<const float*>(patch2[b]);
#pragma unroll
            for (int ch = 0; ch < 2; ch++) {
                if (2 * s + ch < C) {
                    ull dup[3][PXW + 2];
#pragma unroll
                    for (int ky = 0; ky < 3; ky++)
#pragma unroll
                        for (int j = 0; j < PXW + 2; j++)
                            dup[ky][j] = packdup(
                                pbf[2 * ((ty + ky) * PS + PXW * px + j) + ch]);

                    const float* wb = &ws[b][ch][coh * GP * 20];
#pragma unroll
                    for (int p = 0; p < GP; p++) {
                        ull w[9];
                        const ulonglong2* q2 = reinterpret_cast<const ulonglong2*>(wb + p * 20);
                        ulonglong2 q0 = q2[0], q1 = q2[1], qq = q2[2], q3 = q2[3];
                        w[0] = q0.x; w[1] = q0.y; w[2] = q1.x; w[3] = q1.y;
                        w[4] = qq.x; w[5] = qq.y; w[6] = q3.x; w[7] = q3.y;
                        w[8] = *reinterpret_cast<const ull*>(wb + p * 20 + 16);
#pragma unroll
                        for (int ky = 0; ky < 3; ky++)
#pragma unroll
                            for (int kx = 0; kx < 3; kx++)
#pragma unroll
                                for (int q = 0; q < PXW; q++)
                                    ffma2(acc[p][q], dup[ky][kx + q], w[ky * 3 + kx]);
                    }
                }
            }
        }

        {
            const int oy = y0 + ty;
            const int ox = x0 + PXW * px;
            float* outp = out + (size_t)n * COUT * HW + (size_t)oy * W + ox;
#pragma unroll
            for (int p = 0; p < GP; p++) {
                int co0 = 2 * (g * COH * GP + coh * GP + p);
                if (co0 < COUT) {
                    float lo[PXW], hi[PXW];
#pragma unroll
                    for (int q = 0; q < PXW; q++) unpack2(acc[p][q], lo[q], hi[q]);
                    float bi0 = __ldg(&bias[co0]);
                    float r[PXW];
#pragma unroll
                    for (int q = 0; q < PXW; q++) {
                        r[q] = lo[q] + bi0;
                        if (RELU) r[q] = fmaxf(r[q], 0.f);
                    }
                    if (PXW == 4)
                        *reinterpret_cast<float4*>(outp + (size_t)co0 * HW) =
                            make_float4(r[0], r[1], r[2], r[3]);
                    else
                        *reinterpret_cast<float2*>(outp + (size_t)co0 * HW) =
                            make_float2(r[0], r[1]);
                    if (co0 + 1 < COUT) {
                        float bi1 = __ldg(&bias[co0 + 1]);
                        float u[PXW];
#pragma unroll
                        for (int q = 0; q < PXW; q++) {
                            u[q] = hi[q] + bi1;
                            if (RELU) u[q] = fmaxf(u[q], 0.f);
                        }
                        if (PXW == 4)
                            *reinterpret_cast<float4*>(outp + (size_t)(co0 + 1) * HW) =
                                make_float4(u[0], u[1], u[2], u[3]);
                        else
                            *reinterpret_cast<float2*>(outp + (size_t)(co0 + 1) * HW) =
                                make_float2(u[0], u[1]);
                    }
                }
            }
        }
        __syncthreads();
    }
}

// ---------------------------------------------------------------------------
// Launch: 5 kernels total.
// ---------------------------------------------------------------------------
extern "C" void kernel_launch(void* const* d_in, const int* in_sizes, int n_in,
                              void* d_out, int out_size)
{
    const float* x   = (const float*)d_in[0];
    const float* g   = (const float*)d_in[1];
    const float* fWa = (const float*)d_in[2];
    const float* fba = (const float*)d_in[3];
    const float* fWb = (const float*)d_in[4];
    const float* fbb = (const float*)d_in[5];
    const float* fWc = (const float*)d_in[6];
    const float* fbc = (const float*)d_in[7];
    const float* W2a = (const float*)d_in[8];
    const float* b2a = (const float*)d_in[9];
    const float* W2b = (const float*)d_in[10];
    const float* b2b = (const float*)d_in[11];
    float* out = (float*)d_out;

    float *h1, *h2, *fbuf, *cat;
    cudaGetSymbolAddress((void**)&h1,   g_h1);
    cudaGetSymbolAddress((void**)&h2,   g_h2);
    cudaGetSymbolAddress((void**)&fbuf, g_f);
    cudaGetSymbolAddress((void**)&cat,  g_cat);

    conv12_all_kernel<<<4768, 128>>>(x, g, fWa, fba, fWb, fbb, h2);
    conv81_all_kernel<<<4768, 128>>>(h2, fWc, fbc, fbuf);
    softmax_all_kernel<<<9536, 128>>>(fbuf, x, g, cat);

    dim3 gridF(512 / 32, 512 / 8, 2);
    conv3x3_kernel<64, true><<<gridF, 128>>>(cat, W2a, b2a, h1, 5, 512, 512);
    conv3x3_kernel<1, false><<<gridF, 128>>>(h1, W2b, b2b, out, 64, 512, 512);
}

// round 15
// speedup vs baseline: 1.4181x; 1.0410x over previous
#include <cuda_runtime.h>
#include <cstdint>

typedef unsigned long long ull;

// ---------------------------------------------------------------------------
// Scale tables. Scale order (big first for launch packing):
//   s=0: x @512 (widx 0, cat ch 0, stride 1)
//   s=1: g @512 (widx 4, cat ch 4, stride 1)
//   s=2: x @256 (widx 1, cat ch 1, stride 2)
//   s=3: x @128 (widx 2, cat ch 2, stride 4)
//   s=4: x @64  (widx 3, cat ch 3, stride 8)
// ---------------------------------------------------------------------------
__constant__ int   c_H[5]      = {512, 512, 256, 128, 64};
__constant__ int   c_stride[5] = {1, 1, 2, 4, 8};
__constant__ int   c_widx[5]   = {0, 4, 1, 2, 3};
__constant__ int   c_isg[5]    = {0, 1, 0, 0, 0};
__constant__ int   c_cboff[6]  = {0, 2048, 4096, 4608, 4736, 4768};
__constant__ int   c_sboff[6]  = {0, 4096, 8192, 9216, 9472, 9536};
__constant__ size_t c_h2off[5] = {0ull, 33554432ull, 67108864ull, 75497472ull, 77594624ull};
__constant__ size_t c_foff[5]  = {0ull, 42467328ull, 84934656ull, 95551488ull, 98205696ull};

// ---------------------------------------------------------------------------
// Scratch (device globals; no allocation anywhere)
// ---------------------------------------------------------------------------
__device__ float g_h1 [(size_t)2 * 64 * 512 * 512];
__device__ float g_h2 [78118912];
__device__ float g_f  [98869248];
__device__ float g_cat[(size_t)2 * 5 * 512 * 512];

// ---------------------------------------------------------------------------
// Packed f32x2 + cp.async helpers
// ---------------------------------------------------------------------------
__device__ __forceinline__ void ffma2(ull& acc, ull a, ull b) {
    asm("fma.rn.f32x2 %0, %1, %2, %0;" : "+l"(acc) : "l"(a), "l"(b));
}
__device__ __forceinline__ ull packdup(float v) {
    ull r;
    asm("mov.b64 %0, {%1, %1};" : "=l"(r) : "f"(v));
    return r;
}
__device__ __forceinline__ ull pack2(float lo, float hi) {
    ull r;
    asm("mov.b64 %0, {%1, %2};" : "=l"(r) : "f"(lo), "f"(hi));
    return r;
}
__device__ __forceinline__ void unpack2(ull v, float& lo, float& hi) {
    asm("mov.b64 {%0, %1}, %2;" : "=f"(lo), "=f"(hi) : "l"(v));
}
__device__ __forceinline__ void cpa4(uint32_t dst, const float* src, bool ok) {
    asm volatile("cp.async.ca.shared.global [%0], [%1], 4, %2;"
                 :: "r"(dst), "l"(src), "r"(ok ? 4 : 0));
}
#define CP_COMMIT() asm volatile("cp.async.commit_group;" ::: "memory")
#define CP_WAIT0()  asm volatile("cp.async.wait_group 0;" ::: "memory")

// ---------------------------------------------------------------------------
// Fused conv1(1->64,relu) + conv2(64->64,relu), ALL SCALES, one launch.
// 4 input channels per barrier stage (NS=16). conv2 weights staged via
// cp.async one stage ahead; conv1 output produced into double-buffered smem
// one stage ahead. ONE __syncthreads per stage.
// ---------------------------------------------------------------------------
__global__ __launch_bounds__(128, 3)
void conv12_all_kernel(const float* __restrict__ x, const float* __restrict__ g,
                       const float* __restrict__ fWa, const float* __restrict__ fba,
                       const float* __restrict__ fWb, const float* __restrict__ fbb,
                       float* __restrict__ h2)
{
    constexpr int GP = 8, NG = 2, COUT = 64;
    constexpr int PS = 35, ROWS = 10;
    constexpr int CELEM = ROWS * 34;            // 340
    constexpr int XPS = 37, XROWS = 12;
    constexpr int XELEM = XROWS * XPS;          // 444
    constexpr int WPC = 2 * GP * 20;            // ws floats per channel slot (320)
    constexpr int WELEM = 2 * GP * 18;          // 288 real elements per channel

    __shared__ float xpatch[XELEM];
    __shared__ ull w1pk[32 * 10];
    __shared__ float2 cbuf[2][2][ROWS * PS];    // [buf][pair-plane][pos]
    __shared__ __align__(16) float ws[2][4][WPC];

    // ---- scale decode ----
    int bid = blockIdx.x;
    int sc;
    if      (bid < c_cboff[1]) sc = 0;
    else if (bid < c_cboff[2]) sc = 1;
    else if (bid < c_cboff[3]) sc = 2;
    else if (bid < c_cboff[4]) sc = 3;
    else                       sc = 4;
    int rem = bid - c_cboff[sc];
    const int H = c_H[sc], W = H;
    const int stride = c_stride[sc];
    const int bw = W >> 5, bh = H >> 3;
    const int n = rem / (bw * bh);  rem -= n * bw * bh;
    const int by = rem / bw, bx = rem - by * bw;
    const int widx = c_widx[sc];
    const float* src = (c_isg[sc] ? g : x) + (size_t)n * 512 * 512;
    const float* w1 = fWa + (size_t)widx * 64 * 9;
    const float* b1 = fba + widx * 64;
    const float* w2 = fWb + (size_t)widx * 64 * 64 * 9;
    const float* b2 = fbb + widx * 64;
    float* out = h2 + c_h2off[sc];

    const int t   = threadIdx.x;
    const int px  = t & 7;
    const int ty  = (t >> 3) & 7;
    const int coh = t >> 6;
    const int x0 = bx << 5;
    const int y0 = by << 3;
    const size_t HW = (size_t)H * W;

    const uint32_t ws_base = (uint32_t)__cvta_generic_to_shared(ws);

    // one-time loads
#pragma unroll
    for (int j = 0; j < 4; j++) {
        int e = t + j * 128;
        if (e < XELEM) {
            int r = e / XPS, cc = e - r * XPS;
            int gy = y0 + r - 2, gx = x0 + cc - 2;
            float v = 0.f;
            if (cc < 36 && gy >= 0 && gy < H && gx >= 0 && gx < W)
                v = src[(size_t)(gy * stride) * 512 + gx * stride];
            xpatch[e] = v;
        }
    }
#pragma unroll
    for (int j = 0; j < 3; j++) {
        int e = t + j * 128;
        if (e < 320) {
            int cp = e / 10, k = e - cp * 10;
            float lo, hi;
            if (k < 9) { lo = w1[(2 * cp) * 9 + k]; hi = w1[(2 * cp + 1) * 9 + k]; }
            else       { lo = b1[2 * cp];           hi = b1[2 * cp + 1]; }
            w1pk[e] = pack2(lo, hi);
        }
    }
    __syncthreads();

    // cp.async fill of conv2 weights for stage s (channels 4s..4s+3), group g2
    auto fill_ws = [&](int bb, int s, int g2) {
#pragma unroll
        for (int cc = 0; cc < 4; cc++) {
            int c = 4 * s + cc;
#pragma unroll
            for (int j = 0; j < 3; j++) {
                int e = t + j * 128;
                if (e < WELEM) {
                    int p2 = e / 18, r = e - p2 * 18;
                    int lane = r / 9, k = r - lane * 9;
                    int co = 2 * (g2 * 16 + p2) + lane;
                    uint32_t dst = ws_base +
                        (uint32_t)(((bb * 4 + cc) * WPC) + p2 * 20 + 2 * k + lane) * 4u;
                    cpa4(dst, w2 + ((size_t)co * 64 + c) * 9 + k, true);
                }
            }
        }
    };

    // produce conv1 channels 4s..4s+3 into cbuf[bb] (two f32x2 pair planes)
    auto produce = [&](int bb, int s) {
#pragma unroll
        for (int pr = 0; pr < 2; pr++) {
            int cp = 2 * s + pr;
            ull w1r[10];
#pragma unroll
            for (int k = 0; k < 10; k++) w1r[k] = w1pk[cp * 10 + k];
#pragma unroll
            for (int j = 0; j < 3; j++) {
                int e = t + j * 128;
                if (e < CELEM) {
                    int r = e / 34, col = e - r * 34;
                    int gy = y0 + r - 1, gx = x0 + col - 1;
                    float2 v = make_float2(0.f, 0.f);
                    if (gy >= 0 && gy < H && gx >= 0 && gx < W) {
                        ull a = w1r[9];
#pragma unroll
                        for (int dy = 0; dy < 3; dy++)
#pragma unroll
                            for (int dx = 0; dx < 3; dx++)
                                ffma2(a, packdup(xpatch[(r + dy) * XPS + col + dx]),
                                      w1r[dy * 3 + dx]);
                        float lo, hi;
                        unpack2(a, lo, hi);
                        v = make_float2(fmaxf(lo, 0.f), fmaxf(hi, 0.f));
                    }
                    cbuf[bb][pr][r * PS + col] = v;
                }
            }
        }
    };

    const float* cbf = reinterpret_cast<const float*>(cbuf);

#pragma unroll 1
    for (int g2 = 0; g2 < NG; ++g2) {
        ull acc[GP][4];
#pragma unroll
        for (int p = 0; p < GP; p++)
#pragma unroll
            for (int q = 0; q < 4; q++) acc[p][q] = 0ull;

        if (g2 == 0) {              // prologue: stage 0 of group 0
            fill_ws(0, 0, 0); CP_COMMIT();
            produce(0, 0);
        }

#pragma unroll 1
        for (int s = 0; s < 16; ++s) {
            int b = s & 1;
            CP_WAIT0();
            __syncthreads();        // ws[b]+cbuf[b] ready; buf b^1 free
            if (s + 1 < 16) {
                fill_ws(b ^ 1, s + 1, g2); CP_COMMIT();
                produce(b ^ 1, s + 1);
            } else if (g2 + 1 < NG) {
                fill_ws(b ^ 1, 0, g2 + 1); CP_COMMIT();
                produce(b ^ 1, 0);
            }

            // consume 4 channels
#pragma unroll
            for (int cc = 0; cc < 4; cc++) {
                const float* pp = cbf + (size_t)(b * 2 + (cc >> 1)) * (ROWS * PS) * 2
                                      + (cc & 1);
                ull dup[3][6];
#pragma unroll
                for (int ky = 0; ky < 3; ky++)
#pragma unroll
                    for (int j = 0; j < 6; j++)
                        dup[ky][j] = packdup(pp[2 * ((ty + ky) * PS + 4 * px + j)]);

                const float* wb = &ws[b][cc][coh * GP * 20];
#pragma unroll
                for (int p = 0; p < GP; p++) {
                    ull w[9];
                    const ulonglong2* q2 = reinterpret_cast<const ulonglong2*>(wb + p * 20);
                    ulonglong2 q0 = q2[0], q1 = q2[1], qq = q2[2], q3 = q2[3];
                    w[0] = q0.x; w[1] = q0.y; w[2] = q1.x; w[3] = q1.y;
                    w[4] = qq.x; w[5] = qq.y; w[6] = q3.x; w[7] = q3.y;
                    w[8] = *reinterpret_cast<const ull*>(wb + p * 20 + 16);
#pragma unroll
                    for (int ky = 0; ky < 3; ky++)
#pragma unroll
                        for (int kx = 0; kx < 3; kx++)
#pragma unroll
                            for (int q = 0; q < 4; q++)
                                ffma2(acc[p][q], dup[ky][kx + q], w[ky * 3 + kx]);
                }
            }
        }

        {
            const int oy = y0 + ty;
            const int ox = x0 + 4 * px;
            float* outp = out + ((size_t)n * COUT) * HW + (size_t)oy * W + ox;
#pragma unroll
            for (int p = 0; p < GP; p++) {
                int co0 = 2 * (g2 * 16 + coh * GP + p);
                float lo[4], hi[4];
#pragma unroll
                for (int q = 0; q < 4; q++) unpack2(acc[p][q], lo[q], hi[q]);
                float bi0 = __ldg(&b2[co0]);
                float bi1 = __ldg(&b2[co0 + 1]);
                float4 r0 = make_float4(fmaxf(lo[0] + bi0, 0.f), fmaxf(lo[1] + bi0, 0.f),
                                        fmaxf(lo[2] + bi0, 0.f), fmaxf(lo[3] + bi0, 0.f));
                float4 r1 = make_float4(fmaxf(hi[0] + bi1, 0.f), fmaxf(hi[1] + bi1, 0.f),
                                        fmaxf(hi[2] + bi1, 0.f), fmaxf(hi[3] + bi1, 0.f));
                *reinterpret_cast<float4*>(outp + (size_t)co0 * HW) = r0;
                *reinterpret_cast<float4*>(outp + (size_t)(co0 + 1) * HW) = r1;
            }
        }
    }
}

// ---------------------------------------------------------------------------
// conv3 (64 -> 81 logits), ALL SCALES, one launch. 4 channels per barrier
// stage (NS=16); patch + weights staged via cp.async one stage ahead.
// COH=2 co-halves across threads, GP=7 pairs, 4 px/thread, NG=3.
// ---------------------------------------------------------------------------
__global__ __launch_bounds__(128, 3)
void conv81_all_kernel(const float* __restrict__ h2, const float* __restrict__ fWc,
                       const float* __restrict__ fbc, float* __restrict__ f)
{
    constexpr int COUT = 81, C = 64;
    constexpr int COH = 2, GP = 7, PXW = 4;
    constexpr int NG = 3;
    constexpr int PS = 35, ROWS = 10;
    constexpr int PELEM = ROWS * PS;            // 350
    constexpr int WPC = COH * GP * 20;          // 280
    constexpr int WELEM = COH * GP * 18;        // 252

    __shared__ float2 pat[2][2][PELEM];         // [buf][pair-plane][pos]
    __shared__ __align__(16) float ws[2][4][WPC];

    // ---- scale decode ----
    int bid = blockIdx.x;
    int sc;
    if      (bid < c_cboff[1]) sc = 0;
    else if (bid < c_cboff[2]) sc = 1;
    else if (bid < c_cboff[3]) sc = 2;
    else if (bid < c_cboff[4]) sc = 3;
    else                       sc = 4;
    int rem = bid - c_cboff[sc];
    const int H = c_H[sc], W = H;
    const int bw = W >> 5, bh = H >> 3;
    const int n = rem / (bw * bh);  rem -= n * bw * bh;
    const int by = rem / bw, bx = rem - by * bw;
    const int widx = c_widx[sc];
    const float* wt = fWc + (size_t)widx * 81 * 64 * 9;
    const float* bias = fbc + widx * 81;
    const size_t HW = (size_t)H * W;
    const float* inn = h2 + c_h2off[sc] + (size_t)n * C * HW;
    float* out = f + c_foff[sc] + (size_t)n * COUT * HW;

    const int t   = threadIdx.x;
    const int px  = t & 7;
    const int ty  = (t >> 3) & 7;
    const int coh = t >> 6;
    const int x0 = bx << 5;
    const int y0 = by << 3;

    const uint32_t pat_base = (uint32_t)__cvta_generic_to_shared(pat);
    const uint32_t ws_base  = (uint32_t)__cvta_generic_to_shared(ws);

    auto fill = [&](int bb, int s, int g2) {
        // patch: channels 4s..4s+3
#pragma unroll
        for (int cc = 0; cc < 4; cc++) {
            int c = 4 * s + cc;
            const float* cbase = inn + (size_t)c * HW;
#pragma unroll
            for (int j = 0; j < 3; j++) {
                int e = t + j * 128;
                if (e < PELEM) {
                    int r = e / PS, col = e - r * PS;
                    int gy = y0 + r - 1, gx = x0 + col - 1;
                    bool ok = (col < 34 && gy >= 0 && gy < H && gx >= 0 && gx < W);
                    int gyc = min(max(gy, 0), H - 1);
                    int gxc = min(max(gx, 0), W - 1);
                    uint32_t dst = pat_base +
                        (uint32_t)((bb * 2 + (cc >> 1)) * PELEM + e) * 8u + (cc & 1) * 4u;
                    cpa4(dst, cbase + (size_t)gyc * W + gxc, ok);
                }
            }
        }
        // weights
#pragma unroll
        for (int cc = 0; cc < 4; cc++) {
            int c = 4 * s + cc;
#pragma unroll
            for (int j = 0; j < 2; j++) {
                int e = t + j * 128;
                if (e < WELEM) {
                    int p2 = e / 18, r = e - p2 * 18;
                    int lane = r / 9, k = r - lane * 9;
                    int co = 2 * (g2 * COH * GP + p2) + lane;
                    bool ok = (co < COUT);
                    int coc = min(co, COUT - 1);
                    uint32_t dst = ws_base +
                        (uint32_t)((bb * 4 + cc) * WPC + p2 * 20 + 2 * k + lane) * 4u;
                    cpa4(dst, wt + ((size_t)coc * C + c) * 9 + k, ok);
                }
            }
        }
    };

    const float* patf = reinterpret_cast<const float*>(pat);

#pragma unroll 1
    for (int g2 = 0; g2 < NG; ++g2) {
        ull acc[GP][PXW];
#pragma unroll
        for (int p = 0; p < GP; p++)
#pragma unroll
            for (int q = 0; q < PXW; q++) acc[p][q] = 0ull;

        if (g2 == 0) { fill(0, 0, 0); CP_COMMIT(); }

#pragma unroll 1
        for (int s = 0; s < 16; ++s) {
            int b = s & 1;
            CP_WAIT0();
            __syncthreads();
            if (s + 1 < 16)      { fill(b ^ 1, s + 1, g2); CP_COMMIT(); }
            else if (g2 + 1 < NG){ fill(b ^ 1, 0, g2 + 1); CP_COMMIT(); }

#pragma unroll
            for (int cc = 0; cc < 4; cc++) {
                const float* pp = patf + (size_t)(b * 2 + (cc >> 1)) * PELEM * 2
                                       + (cc & 1);
                ull dup[3][PXW + 2];
#pragma unroll
                for (int ky = 0; ky < 3; ky++)
#pragma unroll
                    for (int j = 0; j < PXW + 2; j++)
                        dup[ky][j] = packdup(pp[2 * ((ty + ky) * PS + PXW * px + j)]);

                const float* wb = &ws[b][cc][coh * GP * 20];
#pragma unroll
                for (int p = 0; p < GP; p++) {
                    ull w[9];
                    const ulonglong2* q2 = reinterpret_cast<const ulonglong2*>(wb + p * 20);
                    ulonglong2 q0 = q2[0], q1 = q2[1], qq = q2[2], q3 = q2[3];
                    w[0] = q0.x; w[1] = q0.y; w[2] = q1.x; w[3] = q1.y;
                    w[4] = qq.x; w[5] = qq.y; w[6] = q3.x; w[7] = q3.y;
                    w[8] = *reinterpret_cast<const ull*>(wb + p * 20 + 16);
#pragma unroll
                    for (int ky = 0; ky < 3; ky++)
#pragma unroll
                        for (int kx = 0; kx < 3; kx++)
#pragma unroll
                            for (int q = 0; q < PXW; q++)
                                ffma2(acc[p][q], dup[ky][kx + q], w[ky * 3 + kx]);
                }
            }
        }

        {
            const int oy = y0 + ty;
            const int ox = x0 + PXW * px;
            float* outp = out + (size_t)oy * W + ox;
#pragma unroll
            for (int p = 0; p < GP; p++) {
                int co0 = 2 * (g2 * COH * GP + coh * GP + p);
                if (co0 < COUT) {
                    float lo[PXW], hi[PXW];
#pragma unroll
                    for (int q = 0; q < PXW; q++) unpack2(acc[p][q], lo[q], hi[q]);
                    float bi0 = __ldg(&bias[co0]);
                    float4 r0 = make_float4(lo[0] + bi0, lo[1] + bi0,
                                            lo[2] + bi0, lo[3] + bi0);
                    *reinterpret_cast<float4*>(outp + (size_t)co0 * HW) = r0;
                    if (co0 + 1 < COUT) {
                        float bi1 = __ldg(&bias[co0 + 1]);
                        float4 r1 = make_float4(hi[0] + bi1, hi[1] + bi1,
                                                hi[2] + bi1, hi[3] + bi1);
                        *reinterpret_cast<float4*>(outp + (size_t)(co0 + 1) * HW) = r1;
                    }
                }
            }
        }
    }
}

// ---------------------------------------------------------------------------
// Softmax(81) + 9x9 dynamic conv + nearest upsample into concat channel.
// ---------------------------------------------------------------------------
__global__ __launch_bounds__(128)
void softmax_all_kernel(const float* __restrict__ f, const float* __restrict__ x,
                        const float* __restrict__ g, float* __restrict__ cat)
{
    int bid = blockIdx.x;
    int sc;
    if      (bid < c_sboff[1]) sc = 0;
    else if (bid < c_sboff[2]) sc = 1;
    else if (bid < c_sboff[3]) sc = 2;
    else if (bid < c_sboff[4]) sc = 3;
    else                       sc = 4;
    int rem = bid - c_sboff[sc];
    const int H = c_H[sc], W = H;
    const int stride = c_stride[sc];
    const int nbp = (H * W + 127) / 128;
    const int n = rem / nbp;
    const int idx = (rem - n * nbp) * 128 + threadIdx.x;
    if (idx >= H * W) return;
    const int iy = idx / W, ix = idx - iy * W;
    const int ch = c_widx[sc];
    const int factor = 512 / H;

    const float* fn = f + c_foff[sc] + (size_t)n * 81 * H * W + idx;
    float lg[81];
    float mx = -1e30f;
#pragma unroll
    for (int k = 0; k < 81; k++) {
        lg[k] = fn[(size_t)k * H * W];
        mx = fmaxf(mx, lg[k]);
    }
    float sum = 0.f;
#pragma unroll
    for (int k = 0; k < 81; k++) {
        lg[k] = __expf(lg[k] - mx);
        sum += lg[k];
    }
    float inv = 1.f / sum;

    const float* sn = (c_isg[sc] ? g : x) + (size_t)n * 512 * 512;
    float outv = 0.f;
#pragma unroll
    for (int dy = 0; dy < 9; dy++) {
        int yy = iy + dy - 4;
#pragma unroll
        for (int dx = 0; dx < 9; dx++) {
            int xx = ix + dx - 4;
            float xv = (yy >= 0 && yy < H && xx >= 0 && xx < W)
                         ? sn[(size_t)(yy * stride) * 512 + xx * stride] : 0.f;
            outv += lg[dy * 9 + dx] * xv;
        }
    }
    outv *= inv;

    float* cn = cat + ((size_t)n * 5 + ch) * 512 * 512;
    int oy0 = iy * factor, ox0 = ix * factor;
    for (int ry = 0; ry < factor; ry++)
        for (int rx = 0; rx < factor; rx++)
            cn[(size_t)(oy0 + ry) * 512 + ox0 + rx] = outv;
}

// ---------------------------------------------------------------------------
// Generic direct 3x3 SAME conv (final 5->64 and 64->1). R8/R10 structure.
// ---------------------------------------------------------------------------
template<int COUT, bool RELU>
__global__ __launch_bounds__(128, 3)
void conv3x3_kernel(const float* __restrict__ in, const float* __restrict__ wt,
                    const float* __restrict__ bias, float* __restrict__ out,
                    int C, int H, int W)
{
    constexpr int COH = (COUT >= 64) ? 2 : 1;
    constexpr int GP  = (COUT == 81) ? 7 : (COUT >= 64 ? 8 : (COUT + 1) / 2);
    constexpr int PXW = (COH == 2) ? 4 : 2;
    constexpr int NPAIR = (COUT + 1) / 2;
    constexpr int NG = (NPAIR + COH * GP - 1) / (COH * GP);
    constexpr int PS = 35, ROWS = 10;
    constexpr int PELEM = ROWS * PS;
    constexpr int WELEM = COH * GP * 18;
    constexpr int WITER = (WELEM + 127) / 128;

    __shared__ float2 patch2[2][PELEM];
    __shared__ __align__(16) float ws[2][2][COH * GP * 20];

    const int t   = threadIdx.x;
    const int px  = (COH == 2) ? (t & 7) : (t & 15);
    const int ty  = (COH == 2) ? ((t >> 3) & 7) : (t >> 4);
    const int coh = (COH == 2) ? (t >> 6) : 0;
    const int x0 = blockIdx.x << 5;
    const int y0 = blockIdx.y << 3;
    const int n  = blockIdx.z;
    const size_t HW = (size_t)H * W;
    const int NS = (C + 1) / 2;

    const float* inn = in + (size_t)n * C * HW;

    float pv[2][3];
    float pw[2][WITER];

    auto prefetch = [&](int g, int s) {
#pragma unroll
        for (int ch = 0; ch < 2; ch++) {
            int c = 2 * s + ch;
#pragma unroll
            for (int j = 0; j < 3; j++) {
                float v = 0.f;
                int e = t + j * 128;
                if (c < C && e < PELEM) {
                    int r = e / PS, cc = e - r * PS;
                    int gy = y0 + r - 1, gx = x0 + cc - 1;
                    if (cc < 34 && gy >= 0 && gy < H && gx >= 0 && gx < W)
                        v = inn[(size_t)c * HW + (size_t)gy * W + gx];
                }
                pv[ch][j] = v;
            }
#pragma unroll
            for (int j = 0; j < WITER; j++) {
                pw[ch][j] = 0.f;
                int e = t + j * 128;
                if (c < C && e < WELEM) {
                    int p2 = e / 18, r = e - p2 * 18;
                    int lane = r / 9, k = r - lane * 9;
                    int co = 2 * (g * COH * GP + p2) + lane;
                    if (co < COUT)
                        pw[ch][j] = wt[((size_t)co * C + c) * 9 + k];
                }
            }
        }
    };

    auto store_sm = [&](int b, int s) {
#pragma unroll
        for (int j = 0; j < 3; j++) {
            int e = t + j * 128;
            if (e < PELEM) patch2[b][e] = make_float2(pv[0][j], pv[1][j]);
        }
#pragma unroll
        for (int ch = 0; ch < 2; ch++)
#pragma unroll
            for (int j = 0; j < WITER; j++) {
                int e = t + j * 128;
                if (e < WELEM) {
                    int p2 = e / 18, r = e - p2 * 18;
                    int lane = r / 9, k = r - lane * 9;
                    ws[b][ch][p2 * 20 + 2 * k + lane] = pw[ch][j];
                }
            }
    };

#pragma unroll 1
    for (int g = 0; g < NG; ++g) {
        ull acc[GP][PXW];
#pragma unroll
        for (int p = 0; p < GP; p++)
#pragma unroll
            for (int q = 0; q < PXW; q++) acc[p][q] = 0ull;

        prefetch(g, 0);
#pragma unroll 1
        for (int s = 0; s < NS; ++s) {
            int b = s & 1;
            store_sm(b, s);
            __syncthreads();
            if (s + 1 < NS) prefetch(g, s + 1);

            const float* pbf = reinterpret_cast<const float*>(patch2[b]);
#pragma unroll
            for (int ch = 0; ch < 2; ch++) {
                if (2 * s + ch < C) {
                    ull dup[3][PXW + 2];
#pragma unroll
                    for (int ky = 0; ky < 3; ky++)
#pragma unroll
                        for (int j = 0; j < PXW + 2; j++)
                            dup[ky][j] = packdup(
                                pbf[2 * ((ty + ky) * PS + PXW * px + j) + ch]);

                    const float* wb = &ws[b][ch][coh * GP * 20];
#pragma unroll
                    for (int p = 0; p < GP; p++) {
                        ull w[9];
                        const ulonglong2* q2 = reinterpret_cast<const ulonglong2*>(wb + p * 20);
                        ulonglong2 q0 = q2[0], q1 = q2[1], qq = q2[2], q3 = q2[3];
                        w[0] = q0.x; w[1] = q0.y; w[2] = q1.x; w[3] = q1.y;
                        w[4] = qq.x; w[5] = qq.y; w[6] = q3.x; w[7] = q3.y;
                        w[8] = *reinterpret_cast<const ull*>(wb + p * 20 + 16);
#pragma unroll
                        for (int ky = 0; ky < 3; ky++)
#pragma unroll
                            for (int kx = 0; kx < 3; kx++)
#pragma unroll
                                for (int q = 0; q < PXW; q++)
                                    ffma2(acc[p][q], dup[ky][kx + q], w[ky * 3 + kx]);
                    }
                }
            }
        }

        {
            const int oy = y0 + ty;
            const int ox = x0 + PXW * px;
            float* outp = out + (size_t)n * COUT * HW + (size_t)oy * W + ox;
#pragma unroll
            for (int p = 0; p < GP; p++) {
                int co0 = 2 * (g * COH * GP + coh * GP + p);
                if (co0 < COUT) {
                    float lo[PXW], hi[PXW];
#pragma unroll
                    for (int q = 0; q < PXW; q++) unpack2(acc[p][q], lo[q], hi[q]);
                    float bi0 = __ldg(&bias[co0]);
                    float r[PXW];
#pragma unroll
                    for (int q = 0; q < PXW; q++) {
                        r[q] = lo[q] + bi0;
                        if (RELU) r[q] = fmaxf(r[q], 0.f);
                    }
                    if (PXW == 4)
                        *reinterpret_cast<float4*>(outp + (size_t)co0 * HW) =
                            make_float4(r[0], r[1], r[2], r[3]);
                    else
                        *reinterpret_cast<float2*>(outp + (size_t)co0 * HW) =
                            make_float2(r[0], r[1]);
                    if (co0 + 1 < COUT) {
                        float bi1 = __ldg(&bias[co0 + 1]);
                        float u[PXW];
#pragma unroll
                        for (int q = 0; q < PXW; q++) {
                            u[q] = hi[q] + bi1;
                            if (RELU) u[q] = fmaxf(u[q], 0.f);
                        }
                        if (PXW == 4)
                            *reinterpret_cast<float4*>(outp + (size_t)(co0 + 1) * HW) =
                                make_float4(u[0], u[1], u[2], u[3]);
                        else
                            *reinterpret_cast<float2*>(outp + (size_t)(co0 + 1) * HW) =
                                make_float2(u[0], u[1]);
                    }
                }
            }
        }
        __syncthreads();
    }
}

// ---------------------------------------------------------------------------
// Launch: 5 kernels total.
// ---------------------------------------------------------------------------
extern "C" void kernel_launch(void* const* d_in, const int* in_sizes, int n_in,
                              void* d_out, int out_size)
{
    const float* x   = (const float*)d_in[0];
    const float* g   = (const float*)d_in[1];
    const float* fWa = (const float*)d_in[2];
    const float* fba = (const float*)d_in[3];
    const float* fWb = (const float*)d_in[4];
    const float* fbb = (const float*)d_in[5];
    const float* fWc = (const float*)d_in[6];
    const float* fbc = (const float*)d_in[7];
    const float* W2a = (const float*)d_in[8];
    const float* b2a = (const float*)d_in[9];
    const float* W2b = (const float*)d_in[10];
    const float* b2b = (const float*)d_in[11];
    float* out = (float*)d_out;

    float *h1, *h2, *fbuf, *cat;
    cudaGetSymbolAddress((void**)&h1,   g_h1);
    cudaGetSymbolAddress((void**)&h2,   g_h2);
    cudaGetSymbolAddress((void**)&fbuf, g_f);
    cudaGetSymbolAddress((void**)&cat,  g_cat);

    conv12_all_kernel<<<4768, 128>>>(x, g, fWa, fba, fWb, fbb, h2);
    conv81_all_kernel<<<4768, 128>>>(h2, fWc, fbc, fbuf);
    softmax_all_kernel<<<9536, 128>>>(fbuf, x, g, cat);

    dim3 gridF(512 / 32, 512 / 8, 2);
    conv3x3_kernel<64, true><<<gridF, 128>>>(cat, W2a, b2a, h1, 5, 512, 512);
    conv3x3_kernel<1, false><<<gridF, 128>>>(h1, W2b, b2b, out, 64, 512, 512);
}